// round 2
// baseline (speedup 1.0000x reference)
#include <cuda_runtime.h>
#include <cstdint>

// ---------------------------------------------------------------------------
// Transformer block via bf16x3 split-precision tensor-core GEMMs.
// Every operand lives as packed u32 = (bf16 hi | bf16 lo << 16); each MMA tile
// is computed as Ah*Bh + Al*Bh + Ah*Bl with fp32 accumulation (~1e-5 rel err).
// B=384, S=128, E=512, H=4, D=128, F=2048.
// ---------------------------------------------------------------------------

constexpr int Bb = 384, Ss = 128, Ee = 512, Hh = 4, Dd = 128, Ff = 2048;
constexpr int MM = Bb * Ss;                       // 49152 tokens

// -------------------- scratch (static device arrays) -----------------------
__device__ uint32_t g_xp   [(size_t)MM * Ee];
__device__ uint32_t g_qp   [(size_t)MM * Ee];
__device__ uint32_t g_kp   [(size_t)MM * Ee];
__device__ uint32_t g_vp   [(size_t)MM * Ee];
__device__ uint32_t g_attnp[(size_t)MM * Ee];
__device__ float    g_x1f  [(size_t)MM * Ee];
__device__ uint32_t g_x1p  [(size_t)MM * Ee];
__device__ uint32_t g_hp   [(size_t)MM * Ff];
__device__ uint32_t g_wqp  [(size_t)Ee * Ee];
__device__ uint32_t g_wkp  [(size_t)Ee * Ee];
__device__ uint32_t g_wvp  [(size_t)Ee * Ee];
__device__ uint32_t g_wop  [(size_t)Ee * Ee];
__device__ uint32_t g_w1p  [(size_t)Ee * Ff];
__device__ uint32_t g_w2p  [(size_t)Ff * Ee];

// -------------------- helpers ----------------------------------------------
__device__ __forceinline__ uint32_t pack2(float x) {      // (bf16 hi | bf16 lo<<16)
    uint16_t hb, lb; float hf;
    asm("cvt.rn.bf16.f32 %0, %1;" : "=h"(hb) : "f"(x));
    asm("cvt.f32.bf16 %0, %1;"    : "=f"(hf) : "h"(hb));
    asm("cvt.rn.bf16.f32 %0, %1;" : "=h"(lb) : "f"(x - hf));
    return (uint32_t)hb | ((uint32_t)lb << 16);
}
// w0 packs element k, w1 packs element k+1 -> hi-pair and lo-pair bf16x2 regs
__device__ __forceinline__ void unzip(uint32_t w0, uint32_t w1,
                                      uint32_t& hi, uint32_t& lo) {
    asm("prmt.b32 %0, %1, %2, 0x5410;" : "=r"(hi) : "r"(w0), "r"(w1));
    asm("prmt.b32 %0, %1, %2, 0x7632;" : "=r"(lo) : "r"(w0), "r"(w1));
}
__device__ __forceinline__ void mma16(float* d, const uint32_t* a,
                                      uint32_t b0, uint32_t b1) {
    asm volatile(
        "mma.sync.aligned.m16n8k16.row.col.f32.bf16.bf16.f32 "
        "{%0,%1,%2,%3}, {%4,%5,%6,%7}, {%8,%9}, {%0,%1,%2,%3};\n"
        : "+f"(d[0]), "+f"(d[1]), "+f"(d[2]), "+f"(d[3])
        : "r"(a[0]), "r"(a[1]), "r"(a[2]), "r"(a[3]), "r"(b0), "r"(b1));
}
__device__ __forceinline__ void mma3(float* d, const uint32_t* ah, const uint32_t* al,
                                     const uint32_t* bh, const uint32_t* bl) {
    mma16(d, ah, bh[0], bh[1]);
    mma16(d, al, bh[0], bh[1]);
    mma16(d, ah, bl[0], bl[1]);
}

// ---------------------------------------------------------------------------
// prep kernels: split x, transpose+split weights (cheap, run inside graph)
// ---------------------------------------------------------------------------
__global__ void pack_kernel(const float* __restrict__ in, uint32_t* __restrict__ out) {
    const int i = (blockIdx.x * blockDim.x + threadIdx.x) * 4;
    const float4 v = *(const float4*)(in + i);
    uint4 o;
    o.x = pack2(v.x); o.y = pack2(v.y); o.z = pack2(v.z); o.w = pack2(v.w);
    *(uint4*)(out + i) = o;
}

__global__ void tpack_kernel(const float* __restrict__ W, uint32_t* __restrict__ Wp,
                             int K, int N) {   // W[K][N] -> Wp[N][K] packed
    __shared__ uint32_t tile[32][33];
    const int kb = blockIdx.y * 32, nb = blockIdx.x * 32;
    const int tx = threadIdx.x & 31, ty = threadIdx.x >> 5;    // 256 thr: ty 0..7
    for (int j = ty; j < 32; j += 8)
        tile[j][tx] = pack2(W[(size_t)(kb + j) * N + nb + tx]);
    __syncthreads();
    for (int j = ty; j < 32; j += 8)
        Wp[(size_t)(nb + j) * K + kb + tx] = tile[tx][j];
}

// ---------------------------------------------------------------------------
// bf16x3 GEMM: C = epi(A[M,K] @ B[K,N] + bias [, res])
// Ap packed [M][K]; Bp packed [N][K] (pre-transposed weights).
// EPI: 0 = packed out; 1 = res, f32 out + packed out; 2 = relu, packed out;
//      3 = res, f32 out (final).
// 128x128x32 tiles, 256 thr, warp grid 2(M)x4(N), warp tile 64x32.
// ---------------------------------------------------------------------------
constexpr int SMEM_GEMM = 2 * (128 * 32 + 128 * 32) * 4;   // 65536 B

template <int EPI>
__device__ __forceinline__ void epi2(float* __restrict__ Cf, uint32_t* __restrict__ Cp,
                                     const float* __restrict__ bias,
                                     const float* __restrict__ res,
                                     int r, int c, int N, float v0, float v1) {
    v0 += bias[c]; v1 += bias[c + 1];
    if (EPI == 1 || EPI == 3) {
        const float2 rv = *(const float2*)(res + (size_t)r * N + c);
        v0 += rv.x; v1 += rv.y;
    }
    if (EPI == 2) { v0 = fmaxf(v0, 0.f); v1 = fmaxf(v1, 0.f); }
    if (EPI == 1 || EPI == 3)
        *(float2*)(Cf + (size_t)r * N + c) = make_float2(v0, v1);
    if (EPI != 3) {
        uint2 o; o.x = pack2(v0); o.y = pack2(v1);
        *(uint2*)(Cp + (size_t)r * N + c) = o;
    }
}

template <int EPI>
__global__ __launch_bounds__(256, 1)
void gemm_bf16x3(const uint32_t* __restrict__ Ap, const uint32_t* __restrict__ Bp,
                 const float* __restrict__ bias, const float* __restrict__ res,
                 float* __restrict__ Cf, uint32_t* __restrict__ Cp,
                 int N, int K) {
    extern __shared__ uint32_t sm[];
    uint32_t* As = sm;             // 2 stages of [128][32] swizzled
    uint32_t* Bs = sm + 2 * 4096;  // 2 stages of [128][32] swizzled

    const int tid = threadIdx.x;
    const int wid = tid >> 5, lane = tid & 31;
    const int g = lane >> 2, q = lane & 3;
    const int wm = wid & 1, wn = wid >> 1;
    const int mB = blockIdx.y * 128, nB = blockIdx.x * 128;

    // cooperative load indexing: 128 rows x 8 u128 per tile, 4 chunks/thread
    int row[4], col4[4], scol[4];
#pragma unroll
    for (int i = 0; i < 4; i++) {
        const int s = tid + i * 256;
        row[i]  = s >> 3;
        col4[i] = (s & 7) << 2;
        scol[i] = col4[i] ^ ((row[i] & 7) << 2);
    }

    const uint32_t* Ag = Ap + (size_t)mB * K;
    const uint32_t* Bg = Bp + (size_t)nB * K;

    uint4 ra[4], rb[4];
    auto loadRegs = [&](int t) {
        const int k0 = t * 32;
#pragma unroll
        for (int i = 0; i < 4; i++) {
            ra[i] = *(const uint4*)(Ag + (size_t)row[i] * K + k0 + col4[i]);
            rb[i] = *(const uint4*)(Bg + (size_t)row[i] * K + k0 + col4[i]);
        }
    };
    auto storeSmem = [&](int st) {
        uint32_t* as = As + st * 4096;
        uint32_t* bs = Bs + st * 4096;
#pragma unroll
        for (int i = 0; i < 4; i++) {
            *(uint4*)(as + row[i] * 32 + scol[i]) = ra[i];
            *(uint4*)(bs + row[i] * 32 + scol[i]) = rb[i];
        }
    };

    float acc[4][4][4];
#pragma unroll
    for (int a = 0; a < 4; a++)
#pragma unroll
        for (int b = 0; b < 4; b++)
#pragma unroll
            for (int c = 0; c < 4; c++) acc[a][b][c] = 0.f;

    const int nT = K / 32;
    const int sw = g << 2;                 // per-thread XOR swizzle (rows ≡ g mod 8)
    loadRegs(0);
    storeSmem(0);
    __syncthreads();

    for (int t = 0; t < nT; ++t) {
        if (t + 1 < nT) loadRegs(t + 1);

        const uint32_t* as = As + (t & 1) * 4096;
        const uint32_t* bs = Bs + (t & 1) * 4096;
#pragma unroll
        for (int kk = 0; kk < 2; kk++) {
            const int kb = kk * 16;
            const int c0 = (kb + 2 * q) ^ sw;         // k-pair word
            const int c1 = (kb + 2 * q + 8) ^ sw;     // k-pair word +8

            uint32_t ah[4][4], al[4][4];
#pragma unroll
            for (int mi = 0; mi < 4; mi++) {
                const int r0 = wm * 64 + mi * 16 + g;
                const uint2 w00 = *(const uint2*)(as + r0 * 32 + c0);
                const uint2 w10 = *(const uint2*)(as + (r0 + 8) * 32 + c0);
                const uint2 w01 = *(const uint2*)(as + r0 * 32 + c1);
                const uint2 w11 = *(const uint2*)(as + (r0 + 8) * 32 + c1);
                unzip(w00.x, w00.y, ah[mi][0], al[mi][0]);
                unzip(w10.x, w10.y, ah[mi][1], al[mi][1]);
                unzip(w01.x, w01.y, ah[mi][2], al[mi][2]);
                unzip(w11.x, w11.y, ah[mi][3], al[mi][3]);
            }
            uint32_t bh[4][2], bl[4][2];
#pragma unroll
            for (int ni = 0; ni < 4; ni++) {
                const int n0 = wn * 32 + ni * 8 + g;
                const uint2 u0 = *(const uint2*)(bs + n0 * 32 + c0);
                const uint2 u1 = *(const uint2*)(bs + n0 * 32 + c1);
                unzip(u0.x, u0.y, bh[ni][0], bl[ni][0]);
                unzip(u1.x, u1.y, bh[ni][1], bl[ni][1]);
            }
#pragma unroll
            for (int mi = 0; mi < 4; mi++)
#pragma unroll
                for (int ni = 0; ni < 4; ni++)
                    mma3(acc[mi][ni], ah[mi], al[mi], bh[ni], bl[ni]);
        }

        if (t + 1 < nT) {
            storeSmem((t + 1) & 1);
            __syncthreads();
        }
    }

#pragma unroll
    for (int mi = 0; mi < 4; mi++) {
        const int r0 = mB + wm * 64 + mi * 16 + g;
#pragma unroll
        for (int ni = 0; ni < 4; ni++) {
            const int c = nB + wn * 32 + ni * 8 + 2 * q;
            epi2<EPI>(Cf, Cp, bias, res, r0,     c, N, acc[mi][ni][0], acc[mi][ni][1]);
            epi2<EPI>(Cf, Cp, bias, res, r0 + 8, c, N, acc[mi][ni][2], acc[mi][ni][3]);
        }
    }
}

// ---------------------------------------------------------------------------
// Attention: one CTA per (b,h). Packed Q,K,V in smem; bf16x3 score MMAs,
// fp32 softmax; P packed into K region, V smem-transposed into Q region;
// bf16x3 P@V; packed output.
// ---------------------------------------------------------------------------
constexpr int SMEM_ATTN = 3 * 128 * 128 * 4;    // 196608 B

__global__ __launch_bounds__(256, 1)
void attn_kernel(const uint32_t* __restrict__ Qp, const uint32_t* __restrict__ Kp,
                 const uint32_t* __restrict__ Vp, uint32_t* __restrict__ Op) {
    extern __shared__ uint32_t sm[];
    uint32_t* Qs = sm;               // 128x128, later reused as V^T
    uint32_t* Ks = sm + 16384;       // 128x128, later reused as P
    uint32_t* Vs = sm + 32768;       // 128x128

    const int tid = threadIdx.x;
    const int bh  = blockIdx.x;
    const size_t base = (size_t)(bh >> 2) * (Ss * Ee) + (bh & 3) * Dd;

    // load Q,K,V tiles (u128, swizzled smem)
    for (int idx = tid; idx < 128 * 32; idx += 256) {
        const int r = idx >> 5, c4 = (idx & 31) << 2;
        const int sc = c4 ^ ((r & 7) << 2);
        const size_t go = base + (size_t)r * Ee + c4;
        *(uint4*)(Qs + r * 128 + sc) = *(const uint4*)(Qp + go);
        *(uint4*)(Ks + r * 128 + sc) = *(const uint4*)(Kp + go);
        *(uint4*)(Vs + r * 128 + sc) = *(const uint4*)(Vp + go);
    }
    __syncthreads();

    const int wid = tid >> 5, lane = tid & 31;
    const int g = lane >> 2, q = lane & 3;
    const int rbase = wid * 16;
    const int sw = g << 2;

    // ---- scores = Q @ K^T (bf16x3), warp: 16 queries x 128 keys ----
    float acc[16][4];
#pragma unroll
    for (int j = 0; j < 16; j++)
#pragma unroll
        for (int c = 0; c < 4; c++) acc[j][c] = 0.f;

#pragma unroll
    for (int kk = 0; kk < 8; kk++) {
        const int c0 = (kk * 16 + 2 * q) ^ sw;
        const int c1 = (kk * 16 + 2 * q + 8) ^ sw;
        uint32_t ah[4], al[4];
        {
            const int r0 = rbase + g;
            const uint2 w00 = *(const uint2*)(Qs + r0 * 128 + c0);
            const uint2 w10 = *(const uint2*)(Qs + (r0 + 8) * 128 + c0);
            const uint2 w01 = *(const uint2*)(Qs + r0 * 128 + c1);
            const uint2 w11 = *(const uint2*)(Qs + (r0 + 8) * 128 + c1);
            unzip(w00.x, w00.y, ah[0], al[0]);
            unzip(w10.x, w10.y, ah[1], al[1]);
            unzip(w01.x, w01.y, ah[2], al[2]);
            unzip(w11.x, w11.y, ah[3], al[3]);
        }
#pragma unroll
        for (int j = 0; j < 16; j++) {
            const int n0 = j * 8 + g;
            const uint2 u0 = *(const uint2*)(Ks + n0 * 128 + c0);
            const uint2 u1 = *(const uint2*)(Ks + n0 * 128 + c1);
            uint32_t bh0[2], bl0[2];
            unzip(u0.x, u0.y, bh0[0], bl0[0]);
            unzip(u1.x, u1.y, bh0[1], bl0[1]);
            mma3(acc[j], ah, al, bh0, bl0);
        }
    }
    __syncthreads();    // all warps done reading Qs/Ks before they're reused

    // ---- softmax (fp32) over 128 cols; rows rbase+g, rbase+g+8 ----
    float m0 = -1e30f, m1 = -1e30f;
#pragma unroll
    for (int j = 0; j < 16; j++) {
        m0 = fmaxf(m0, fmaxf(acc[j][0], acc[j][1]));
        m1 = fmaxf(m1, fmaxf(acc[j][2], acc[j][3]));
    }
    m0 = fmaxf(m0, __shfl_xor_sync(0xffffffffu, m0, 1));
    m0 = fmaxf(m0, __shfl_xor_sync(0xffffffffu, m0, 2));
    m1 = fmaxf(m1, __shfl_xor_sync(0xffffffffu, m1, 1));
    m1 = fmaxf(m1, __shfl_xor_sync(0xffffffffu, m1, 2));
    float s0 = 0.f, s1 = 0.f;
#pragma unroll
    for (int j = 0; j < 16; j++) {
        acc[j][0] = expf(acc[j][0] - m0);
        acc[j][1] = expf(acc[j][1] - m0);
        acc[j][2] = expf(acc[j][2] - m1);
        acc[j][3] = expf(acc[j][3] - m1);
        s0 += acc[j][0] + acc[j][1];
        s1 += acc[j][2] + acc[j][3];
    }
    s0 += __shfl_xor_sync(0xffffffffu, s0, 1);
    s0 += __shfl_xor_sync(0xffffffffu, s0, 2);
    s1 += __shfl_xor_sync(0xffffffffu, s1, 1);
    s1 += __shfl_xor_sync(0xffffffffu, s1, 2);
    const float r0s = 1.f / s0, r1s = 1.f / s1;

    // store packed P into Ks region (warp-private rows)
    uint32_t* Ps = Ks;
#pragma unroll
    for (int j = 0; j < 16; j++) {
        const int cc = (j * 8 + 2 * q) ^ sw;
        uint2 o0, o1;
        o0.x = pack2(acc[j][0] * r0s); o0.y = pack2(acc[j][1] * r0s);
        o1.x = pack2(acc[j][2] * r1s); o1.y = pack2(acc[j][3] * r1s);
        *(uint2*)(Ps + (rbase + g) * 128 + cc)     = o0;
        *(uint2*)(Ps + (rbase + g + 8) * 128 + cc) = o1;
    }

    // transpose V into Qs region: Vt[f][k] = Vs[k][f]
    uint32_t* Vt = Qs;
#pragma unroll
    for (int ii = 0; ii < 16; ii++) {
        const int f = wid * 16 + ii;
#pragma unroll
        for (int j = 0; j < 4; j++) {
            const int k = lane + 32 * j;
            const uint32_t v = Vs[k * 128 + (f ^ ((k & 7) << 2))];
            Vt[f * 128 + (k ^ ((f & 7) << 2))] = v;
        }
    }
    __syncthreads();

    // ---- out = P @ V (bf16x3) ----
    float acc2[16][4];
#pragma unroll
    for (int j = 0; j < 16; j++)
#pragma unroll
        for (int c = 0; c < 4; c++) acc2[j][c] = 0.f;

#pragma unroll
    for (int kk = 0; kk < 8; kk++) {
        const int c0 = (kk * 16 + 2 * q) ^ sw;
        const int c1 = (kk * 16 + 2 * q + 8) ^ sw;
        uint32_t ah[4], al[4];
        {
            const int rr = rbase + g;
            const uint2 w00 = *(const uint2*)(Ps + rr * 128 + c0);
            const uint2 w10 = *(const uint2*)(Ps + (rr + 8) * 128 + c0);
            const uint2 w01 = *(const uint2*)(Ps + rr * 128 + c1);
            const uint2 w11 = *(const uint2*)(Ps + (rr + 8) * 128 + c1);
            unzip(w00.x, w00.y, ah[0], al[0]);
            unzip(w10.x, w10.y, ah[1], al[1]);
            unzip(w01.x, w01.y, ah[2], al[2]);
            unzip(w11.x, w11.y, ah[3], al[3]);
        }
#pragma unroll
        for (int j = 0; j < 16; j++) {
            const int n0 = j * 8 + g;
            const uint2 u0 = *(const uint2*)(Vt + n0 * 128 + c0);
            const uint2 u1 = *(const uint2*)(Vt + n0 * 128 + c1);
            uint32_t bh0[2], bl0[2];
            unzip(u0.x, u0.y, bh0[0], bl0[0]);
            unzip(u1.x, u1.y, bh0[1], bl0[1]);
            mma3(acc2[j], ah, al, bh0, bl0);
        }
    }

    // ---- packed output ----
#pragma unroll
    for (int j = 0; j < 16; j++) {
        const size_t o0 = base + (size_t)(rbase + g) * Ee + j * 8 + 2 * q;
        uint2 w0, w1;
        w0.x = pack2(acc2[j][0]); w0.y = pack2(acc2[j][1]);
        w1.x = pack2(acc2[j][2]); w1.y = pack2(acc2[j][3]);
        *(uint2*)(Op + o0)                 = w0;
        *(uint2*)(Op + o0 + (size_t)8 * Ee) = w1;
    }
}

// ---------------------------------------------------------------------------
// launch
// ---------------------------------------------------------------------------
extern "C" void kernel_launch(void* const* d_in, const int* in_sizes, int n_in,
                              void* d_out, int out_size) {
    (void)in_sizes; (void)n_in; (void)out_size;

    const float* x  = (const float*)d_in[0];
    const float* wq = (const float*)d_in[1];
    const float* bq = (const float*)d_in[2];
    const float* wk = (const float*)d_in[3];
    const float* bk = (const float*)d_in[4];
    const float* wv = (const float*)d_in[5];
    const float* bv = (const float*)d_in[6];
    const float* wo = (const float*)d_in[7];
    const float* bo = (const float*)d_in[8];
    const float* w1 = (const float*)d_in[9];
    const float* b1 = (const float*)d_in[10];
    const float* w2 = (const float*)d_in[11];
    const float* b2 = (const float*)d_in[12];
    float* out = (float*)d_out;

    uint32_t *xp, *qp, *kp, *vp, *attnp, *x1p, *hp;
    uint32_t *wqp, *wkp, *wvp, *wop, *w1p, *w2p;
    float* x1f;
    cudaGetSymbolAddress((void**)&xp,    g_xp);
    cudaGetSymbolAddress((void**)&qp,    g_qp);
    cudaGetSymbolAddress((void**)&kp,    g_kp);
    cudaGetSymbolAddress((void**)&vp,    g_vp);
    cudaGetSymbolAddress((void**)&attnp, g_attnp);
    cudaGetSymbolAddress((void**)&x1f,   g_x1f);
    cudaGetSymbolAddress((void**)&x1p,   g_x1p);
    cudaGetSymbolAddress((void**)&hp,    g_hp);
    cudaGetSymbolAddress((void**)&wqp,   g_wqp);
    cudaGetSymbolAddress((void**)&wkp,   g_wkp);
    cudaGetSymbolAddress((void**)&wvp,   g_wvp);
    cudaGetSymbolAddress((void**)&wop,   g_wop);
    cudaGetSymbolAddress((void**)&w1p,   g_w1p);
    cudaGetSymbolAddress((void**)&w2p,   g_w2p);

    cudaFuncSetAttribute(gemm_bf16x3<0>, cudaFuncAttributeMaxDynamicSharedMemorySize, SMEM_GEMM);
    cudaFuncSetAttribute(gemm_bf16x3<1>, cudaFuncAttributeMaxDynamicSharedMemorySize, SMEM_GEMM);
    cudaFuncSetAttribute(gemm_bf16x3<2>, cudaFuncAttributeMaxDynamicSharedMemorySize, SMEM_GEMM);
    cudaFuncSetAttribute(gemm_bf16x3<3>, cudaFuncAttributeMaxDynamicSharedMemorySize, SMEM_GEMM);
    cudaFuncSetAttribute(attn_kernel,    cudaFuncAttributeMaxDynamicSharedMemorySize, SMEM_ATTN);

    const dim3 blk(256);

    // prep: split x, transpose+split weights
    pack_kernel<<<(size_t)MM * Ee / 1024, 256>>>(x, xp);
    tpack_kernel<<<dim3(Ee / 32, Ee / 32), 256>>>(wq, wqp, Ee, Ee);
    tpack_kernel<<<dim3(Ee / 32, Ee / 32), 256>>>(wk, wkp, Ee, Ee);
    tpack_kernel<<<dim3(Ee / 32, Ee / 32), 256>>>(wv, wvp, Ee, Ee);
    tpack_kernel<<<dim3(Ee / 32, Ee / 32), 256>>>(wo, wop, Ee, Ee);
    tpack_kernel<<<dim3(Ff / 32, Ee / 32), 256>>>(w1, w1p, Ee, Ff);
    tpack_kernel<<<dim3(Ee / 32, Ff / 32), 256>>>(w2, w2p, Ff, Ee);

    const dim3 gE(Ee / 128, MM / 128);   // (4, 384)
    const dim3 gF(Ff / 128, MM / 128);   // (16, 384)

    // QKV projections (packed outputs)
    gemm_bf16x3<0><<<gE, blk, SMEM_GEMM>>>(xp, wqp, bq, nullptr, nullptr, qp, Ee, Ee);
    gemm_bf16x3<0><<<gE, blk, SMEM_GEMM>>>(xp, wkp, bk, nullptr, nullptr, kp, Ee, Ee);
    gemm_bf16x3<0><<<gE, blk, SMEM_GEMM>>>(xp, wvp, bv, nullptr, nullptr, vp, Ee, Ee);

    // attention
    attn_kernel<<<Bb * Hh, blk, SMEM_ATTN>>>(qp, kp, vp, attnp);

    // x1 = x + attn @ wo + bo   (f32 + packed)
    gemm_bf16x3<1><<<gE, blk, SMEM_GEMM>>>(attnp, wop, bo, x, x1f, x1p, Ee, Ee);

    // h = relu(x1 @ w1 + b1)    (packed)
    gemm_bf16x3<2><<<gF, blk, SMEM_GEMM>>>(x1p, w1p, b1, nullptr, nullptr, hp, Ff, Ee);

    // out = x1 + h @ w2 + b2    (f32 final)
    gemm_bf16x3<3><<<gE, blk, SMEM_GEMM>>>(hp, w2p, b2, x1f, out, nullptr, Ee, Ff);
}

// round 4
// speedup vs baseline: 1.0074x; 1.0074x over previous
#include <cuda_runtime.h>
#include <cstdint>

// ---------------------------------------------------------------------------
// Transformer block, bf16x3 split-precision mma.sync GEMMs (sm_100 baseline
// ISA only — tcgen05 is not available through this toolchain).
// Operands live as separate hi/lo bf16 planes; GEMM hot loop = ldmatrix+HMMA.
// B=384, S=128, E=512, H=4, D=128, F=2048.
// ---------------------------------------------------------------------------

constexpr int Bb = 384, Ss = 128, Ee = 512, Hh = 4, Ff = 2048;
constexpr int MM   = Bb * Ss;          // 49152
constexpr int NQKV = 3 * Ee;           // 1536

// -------------------- scratch (static device arrays) -----------------------
__device__ uint16_t g_xh [(size_t)MM * Ee], g_xl [(size_t)MM * Ee];
__device__ uint32_t g_qkvp[(size_t)MM * NQKV];
__device__ uint16_t g_ath[(size_t)MM * Ee], g_atl[(size_t)MM * Ee];
__device__ float    g_x1f[(size_t)MM * Ee];
__device__ uint16_t g_x1h[(size_t)MM * Ee], g_x1l[(size_t)MM * Ee];
__device__ uint16_t g_hh [(size_t)MM * Ff], g_hl [(size_t)MM * Ff];
__device__ uint16_t g_wqkvh[(size_t)NQKV * Ee], g_wqkvl[(size_t)NQKV * Ee];
__device__ uint16_t g_woh[(size_t)Ee * Ee],  g_wol[(size_t)Ee * Ee];
__device__ uint16_t g_w1h[(size_t)Ff * Ee],  g_w1l[(size_t)Ff * Ee];
__device__ uint16_t g_w2h[(size_t)Ee * Ff],  g_w2l[(size_t)Ee * Ff];
__device__ float    g_bqkv[NQKV];

// -------------------- helpers ----------------------------------------------
__device__ __forceinline__ void split2(float v, uint16_t& h, uint16_t& l) {
    float hf;
    asm("cvt.rn.bf16.f32 %0, %1;" : "=h"(h) : "f"(v));
    asm("cvt.f32.bf16 %0, %1;"    : "=f"(hf) : "h"(h));
    asm("cvt.rn.bf16.f32 %0, %1;" : "=h"(l) : "f"(v - hf));
}
__device__ __forceinline__ uint32_t pack2(float x) {      // (hi | lo<<16)
    uint16_t h, l; split2(x, h, l);
    return (uint32_t)h | ((uint32_t)l << 16);
}
__device__ __forceinline__ uint32_t cvta_s(const void* p) {
    uint32_t a;
    asm("{\n\t.reg .u64 t;\n\tcvta.to.shared.u64 t, %1;\n\tcvt.u32.u64 %0, t;\n\t}"
        : "=r"(a) : "l"(p));
    return a;
}

#define CP16(s, g)  asm volatile("cp.async.cg.shared.global [%0], [%1], 16;" ::"r"(s), "l"(g))
#define CPCOMMIT()  asm volatile("cp.async.commit_group;" ::: "memory")

__device__ __forceinline__ void cpwait(int ahead) {
    if (ahead >= 3)      asm volatile("cp.async.wait_group 3;" ::: "memory");
    else if (ahead == 2) asm volatile("cp.async.wait_group 2;" ::: "memory");
    else if (ahead == 1) asm volatile("cp.async.wait_group 1;" ::: "memory");
    else                 asm volatile("cp.async.wait_group 0;" ::: "memory");
}

#define LDSM4(r0, r1, r2, r3, a) \
    asm volatile("ldmatrix.sync.aligned.m8n8.x4.shared.b16 {%0,%1,%2,%3}, [%4];" \
        : "=r"(r0), "=r"(r1), "=r"(r2), "=r"(r3) : "r"(a))

__device__ __forceinline__ void mma16(float* d, const uint32_t* a,
                                      uint32_t b0, uint32_t b1) {
    asm volatile(
        "mma.sync.aligned.m16n8k16.row.col.f32.bf16.bf16.f32 "
        "{%0,%1,%2,%3}, {%4,%5,%6,%7}, {%8,%9}, {%0,%1,%2,%3};\n"
        : "+f"(d[0]), "+f"(d[1]), "+f"(d[2]), "+f"(d[3])
        : "r"(a[0]), "r"(a[1]), "r"(a[2]), "r"(a[3]), "r"(b0), "r"(b1));
}
__device__ __forceinline__ void unzip(uint32_t w0, uint32_t w1,
                                      uint32_t& hi, uint32_t& lo) {
    asm("prmt.b32 %0, %1, %2, 0x5410;" : "=r"(hi) : "r"(w0), "r"(w1));
    asm("prmt.b32 %0, %1, %2, 0x7632;" : "=r"(lo) : "r"(w0), "r"(w1));
}
__device__ __forceinline__ void mma3(float* d, const uint32_t* ah, const uint32_t* al,
                                     uint32_t bh0, uint32_t bh1,
                                     uint32_t bl0, uint32_t bl1) {
    mma16(d, ah, bh0, bh1);
    mma16(d, al, bh0, bh1);
    mma16(d, ah, bl0, bl1);
}

// ---------------------------------------------------------------------------
// prep: split x into bf16 planes + concat qkv bias
// ---------------------------------------------------------------------------
__global__ void pack_x(const float* __restrict__ x,
                       const float* __restrict__ bq, const float* __restrict__ bk,
                       const float* __restrict__ bv) {
    const int b = blockIdx.x;
    if (b >= 12288) {
        const int i = (b - 12288) * 256 + threadIdx.x;
        if (i < NQKV)
            g_bqkv[i] = i < 512 ? bq[i] : (i < 1024 ? bk[i - 512] : bv[i - 1024]);
        return;
    }
    const size_t base = ((size_t)b * 256 + threadIdx.x) * 8;
    const float4 v0 = *(const float4*)(x + base);
    const float4 v1 = *(const float4*)(x + base + 4);
    uint16_t h[8], l[8];
    split2(v0.x, h[0], l[0]); split2(v0.y, h[1], l[1]);
    split2(v0.z, h[2], l[2]); split2(v0.w, h[3], l[3]);
    split2(v1.x, h[4], l[4]); split2(v1.y, h[5], l[5]);
    split2(v1.z, h[6], l[6]); split2(v1.w, h[7], l[7]);
    uint4 oh, ol;
    oh.x = h[0] | (h[1] << 16); oh.y = h[2] | (h[3] << 16);
    oh.z = h[4] | (h[5] << 16); oh.w = h[6] | (h[7] << 16);
    ol.x = l[0] | (l[1] << 16); ol.y = l[2] | (l[3] << 16);
    ol.z = l[4] | (l[5] << 16); ol.w = l[6] | (l[7] << 16);
    *(uint4*)(g_xh + base) = oh;
    *(uint4*)(g_xl + base) = ol;
}

// transpose + split all weights into [N][K] bf16 planes
__global__ void tpack_all(const float* __restrict__ wq, const float* __restrict__ wk,
                          const float* __restrict__ wv, const float* __restrict__ wo,
                          const float* __restrict__ w1, const float* __restrict__ w2) {
    __shared__ uint32_t tile[32][33];
    const int id = blockIdx.x;
    const float* W; uint16_t *Dh, *Dl;
    int Nsrc, Kd, tx, ty, rowoff = 0;
    if (id < 768) {
        const int w = id >> 8, loc = id & 255;
        tx = loc & 15; ty = loc >> 4;
        W = w == 0 ? wq : (w == 1 ? wk : wv);
        Dh = g_wqkvh; Dl = g_wqkvl; Nsrc = 512; Kd = 512; rowoff = w * 512;
    } else if (id < 1024) {
        const int loc = id - 768; tx = loc & 15; ty = loc >> 4;
        W = wo; Dh = g_woh; Dl = g_wol; Nsrc = 512; Kd = 512;
    } else if (id < 2048) {
        const int loc = id - 1024; tx = loc & 63; ty = loc >> 6;
        W = w1; Dh = g_w1h; Dl = g_w1l; Nsrc = 2048; Kd = 512;
    } else {
        const int loc = id - 2048; tx = loc & 15; ty = loc >> 4;
        W = w2; Dh = g_w2h; Dl = g_w2l; Nsrc = 512; Kd = 2048;
    }
    const int kb = ty * 32, nb = tx * 32;
    const int lx = threadIdx.x & 31, ly = threadIdx.x >> 5;
    for (int j = ly; j < 32; j += 8) {
        uint16_t h, l;
        split2(W[(size_t)(kb + j) * Nsrc + nb + lx], h, l);
        tile[j][lx] = (uint32_t)h | ((uint32_t)l << 16);
    }
    __syncthreads();
    for (int j = ly; j < 32; j += 8) {
        const uint32_t u = tile[lx][j];
        const size_t o = (size_t)(rowoff + nb + j) * Kd + kb + lx;
        Dh[o] = (uint16_t)u;
        Dl[o] = (uint16_t)(u >> 16);
    }
}

// ---------------------------------------------------------------------------
// GEMM: C = epi(A[M,K] @ B[N,K]^T + bias [, res]), bf16x3 via ldmatrix+HMMA.
// CTA tile 256x128, BK=32, 4-stage cp.async pipeline, 8 warps (warp 64x64).
// EPI: 0 = packed-u32 out; 1 = +res, f32 + planes; 2 = relu, planes; 3 = +res, f32.
// ---------------------------------------------------------------------------
constexpr int ST   = 4;
constexpr int STGB = 49152;   // per-stage bytes: Ah 16K | Al 16K | Bh 8K | Bl 8K
constexpr int AH_OFF = 0, AL_OFF = 16384, BH_OFF = 32768, BL_OFF = 40960;
constexpr int SMEM_G = ST * STGB;   // 196608

template <int EPI>
__device__ __forceinline__ void epi2(float* __restrict__ Cf, uint32_t* __restrict__ Cp,
                                     uint16_t* __restrict__ Ch, uint16_t* __restrict__ Cl,
                                     const float* __restrict__ bias,
                                     const float* __restrict__ res,
                                     int r, int c, int N, float v0, float v1) {
    v0 += bias[c]; v1 += bias[c + 1];
    if (EPI == 1 || EPI == 3) {
        const float2 rv = *(const float2*)(res + (size_t)r * N + c);
        v0 += rv.x; v1 += rv.y;
    }
    if (EPI == 2) { v0 = fmaxf(v0, 0.f); v1 = fmaxf(v1, 0.f); }
    if (EPI == 1 || EPI == 3)
        *(float2*)(Cf + (size_t)r * N + c) = make_float2(v0, v1);
    if (EPI == 0) {
        uint2 o; o.x = pack2(v0); o.y = pack2(v1);
        *(uint2*)(Cp + (size_t)r * N + c) = o;
    }
    if (EPI == 1 || EPI == 2) {
        uint16_t h0, l0, h1, l1;
        split2(v0, h0, l0); split2(v1, h1, l1);
        *(uint32_t*)(Ch + (size_t)r * N + c) = (uint32_t)h0 | ((uint32_t)h1 << 16);
        *(uint32_t*)(Cl + (size_t)r * N + c) = (uint32_t)l0 | ((uint32_t)l1 << 16);
    }
}

template <int EPI>
__global__ __launch_bounds__(256, 1)
void gemm_p(const uint16_t* __restrict__ Ah_, const uint16_t* __restrict__ Al_,
            const uint16_t* __restrict__ Bh_, const uint16_t* __restrict__ Bl_,
            const float* __restrict__ bias, const float* __restrict__ res,
            float* __restrict__ Cf, uint32_t* __restrict__ Cp,
            uint16_t* __restrict__ Ch, uint16_t* __restrict__ Cl,
            int Nout, int K) {
    extern __shared__ char smraw[];
    const uint32_t sb = cvta_s(smraw);

    const int tid = threadIdx.x, wid = tid >> 5, lane = tid & 31;
    const int wm = wid >> 1, wn = wid & 1;         // 4(M) x 2(N) warp grid
    const int mB = blockIdx.y * 256, nB = blockIdx.x * 128;
    const int l7 = lane & 7, l8 = (lane >> 3) & 1, l16 = lane >> 4;
    const int swz = l7 & 3;

    float acc[4][8][4];
#pragma unroll
    for (int a = 0; a < 4; a++)
#pragma unroll
        for (int b = 0; b < 8; b++)
#pragma unroll
            for (int c = 0; c < 4; c++) acc[a][b][c] = 0.f;

    auto issue = [&](int s) {
        const uint32_t stb = sb + (s & (ST - 1)) * STGB;
        const int kg = s * 32;
#pragma unroll
        for (int i = 0; i < 12; i++) {
            const int c = tid + i * 256;
            const uint16_t* g; uint32_t d;
            if (c < 2048) {
                const int pl = c >> 10, idx = c & 1023;
                const int row = idx >> 2, ch = idx & 3;
                g = (pl ? Al_ : Ah_) + (size_t)(mB + row) * K + kg + ch * 8;
                d = stb + (pl ? AL_OFF : AH_OFF) + row * 64 + ((ch ^ (row & 3)) << 4);
            } else {
                const int cb = c - 2048;
                const int pl = cb >> 9, idx = cb & 511;
                const int row = idx >> 2, ch = idx & 3;
                g = (pl ? Bl_ : Bh_) + (size_t)(nB + row) * K + kg + ch * 8;
                d = stb + (pl ? BL_OFF : BH_OFF) + row * 64 + ((ch ^ (row & 3)) << 4);
            }
            CP16(d, g);
        }
        CPCOMMIT();
    };

    const int nT = K >> 5;
    for (int s = 0; s < ST - 1 && s < nT; s++) issue(s);

    for (int t = 0; t < nT; t++) {
        if (t + ST - 1 < nT) issue(t + ST - 1);
        const int ahead = nT - 1 - t;
        cpwait(ahead < 3 ? ahead : 3);
        __syncthreads();

        const uint32_t stb = sb + (t & (ST - 1)) * STGB;
#pragma unroll
        for (int h = 0; h < 2; h++) {
            const uint32_t coff = ((2 * h + l16) ^ swz) << 4;
            uint32_t ah[4][4], al[4][4];
#pragma unroll
            for (int mi = 0; mi < 4; mi++) {
                const uint32_t ra = wm * 64 + mi * 16 + l8 * 8 + l7;
                const uint32_t aA = stb + AH_OFF + ra * 64 + coff;
                LDSM4(ah[mi][0], ah[mi][1], ah[mi][2], ah[mi][3], aA);
                LDSM4(al[mi][0], al[mi][1], al[mi][2], al[mi][3],
                      aA + (AL_OFF - AH_OFF));
            }
#pragma unroll
            for (int j2 = 0; j2 < 4; j2++) {
                const uint32_t rb = wn * 64 + j2 * 16 + l8 * 8 + l7;
                const uint32_t aB = stb + BH_OFF + rb * 64 + coff;
                uint32_t bhm[4], blm[4];
                LDSM4(bhm[0], bhm[1], bhm[2], bhm[3], aB);
                LDSM4(blm[0], blm[1], blm[2], blm[3], aB + (BL_OFF - BH_OFF));
#pragma unroll
                for (int mi = 0; mi < 4; mi++) {
#pragma unroll
                    for (int jj = 0; jj < 2; jj++)
                        mma3(acc[mi][2 * j2 + jj], ah[mi], al[mi],
                             bhm[jj], bhm[2 + jj], blm[jj], blm[2 + jj]);
                }
            }
        }
        __syncthreads();
    }

    // epilogue
#pragma unroll
    for (int mi = 0; mi < 4; mi++) {
        const int r0 = mB + wm * 64 + mi * 16 + (lane >> 2);
#pragma unroll
        for (int nj = 0; nj < 8; nj++) {
            const int c = nB + wn * 64 + nj * 8 + 2 * (lane & 3);
            epi2<EPI>(Cf, Cp, Ch, Cl, bias, res, r0,     c, Nout,
                      acc[mi][nj][0], acc[mi][nj][1]);
            epi2<EPI>(Cf, Cp, Ch, Cl, bias, res, r0 + 8, c, Nout,
                      acc[mi][nj][2], acc[mi][nj][3]);
        }
    }
}

// ---------------------------------------------------------------------------
// Attention (mma.sync bf16x3) — reads packed qkv, writes hi/lo planes.
// ---------------------------------------------------------------------------
constexpr int SMEM_ATTN = 3 * 128 * 128 * 4;    // 196608 B

__global__ __launch_bounds__(256, 1)
void attn_kernel(const uint32_t* __restrict__ qkv,
                 uint16_t* __restrict__ Oh, uint16_t* __restrict__ Ol) {
    extern __shared__ uint32_t sm[];
    uint32_t* Qs = sm;               // 128x128, later V^T
    uint32_t* Ks = sm + 16384;       // 128x128, later P
    uint32_t* Vs = sm + 32768;

    const int tid = threadIdx.x;
    const int bh  = blockIdx.x;
    const size_t rowbase = (size_t)(bh >> 2) * Ss * NQKV + (size_t)(bh & 3) * 128;
    const size_t obase   = (size_t)(bh >> 2) * Ss * Ee   + (size_t)(bh & 3) * 128;

    for (int idx = tid; idx < 128 * 32; idx += 256) {
        const int r = idx >> 5, c4 = (idx & 31) << 2;
        const int sc = c4 ^ ((r & 7) << 2);
        const size_t go = rowbase + (size_t)r * NQKV + c4;
        *(uint4*)(Qs + r * 128 + sc) = *(const uint4*)(qkv + go);
        *(uint4*)(Ks + r * 128 + sc) = *(const uint4*)(qkv + go + 512);
        *(uint4*)(Vs + r * 128 + sc) = *(const uint4*)(qkv + go + 1024);
    }
    __syncthreads();

    const int wid = tid >> 5, lane = tid & 31;
    const int g = lane >> 2, q = lane & 3;
    const int rbase = wid * 16;
    const int sw = g << 2;

    float acc[16][4];
#pragma unroll
    for (int j = 0; j < 16; j++)
#pragma unroll
        for (int c = 0; c < 4; c++) acc[j][c] = 0.f;

#pragma unroll
    for (int kk = 0; kk < 8; kk++) {
        const int c0 = (kk * 16 + 2 * q) ^ sw;
        const int c1 = (kk * 16 + 2 * q + 8) ^ sw;
        uint32_t ah[4], al[4];
        {
            const int r0 = rbase + g;
            const uint2 w00 = *(const uint2*)(Qs + r0 * 128 + c0);
            const uint2 w10 = *(const uint2*)(Qs + (r0 + 8) * 128 + c0);
            const uint2 w01 = *(const uint2*)(Qs + r0 * 128 + c1);
            const uint2 w11 = *(const uint2*)(Qs + (r0 + 8) * 128 + c1);
            unzip(w00.x, w00.y, ah[0], al[0]);
            unzip(w10.x, w10.y, ah[1], al[1]);
            unzip(w01.x, w01.y, ah[2], al[2]);
            unzip(w11.x, w11.y, ah[3], al[3]);
        }
#pragma unroll
        for (int j = 0; j < 16; j++) {
            const int n0 = j * 8 + g;
            const uint2 u0 = *(const uint2*)(Ks + n0 * 128 + c0);
            const uint2 u1 = *(const uint2*)(Ks + n0 * 128 + c1);
            uint32_t bh0[2], bl0[2];
            unzip(u0.x, u0.y, bh0[0], bl0[0]);
            unzip(u1.x, u1.y, bh0[1], bl0[1]);
            mma3(acc[j], ah, al, bh0[0], bh0[1], bl0[0], bl0[1]);
        }
    }
    __syncthreads();

    float m0 = -1e30f, m1 = -1e30f;
#pragma unroll
    for (int j = 0; j < 16; j++) {
        m0 = fmaxf(m0, fmaxf(acc[j][0], acc[j][1]));
        m1 = fmaxf(m1, fmaxf(acc[j][2], acc[j][3]));
    }
    m0 = fmaxf(m0, __shfl_xor_sync(0xffffffffu, m0, 1));
    m0 = fmaxf(m0, __shfl_xor_sync(0xffffffffu, m0, 2));
    m1 = fmaxf(m1, __shfl_xor_sync(0xffffffffu, m1, 1));
    m1 = fmaxf(m1, __shfl_xor_sync(0xffffffffu, m1, 2));
    float s0 = 0.f, s1 = 0.f;
#pragma unroll
    for (int j = 0; j < 16; j++) {
        acc[j][0] = expf(acc[j][0] - m0);
        acc[j][1] = expf(acc[j][1] - m0);
        acc[j][2] = expf(acc[j][2] - m1);
        acc[j][3] = expf(acc[j][3] - m1);
        s0 += acc[j][0] + acc[j][1];
        s1 += acc[j][2] + acc[j][3];
    }
    s0 += __shfl_xor_sync(0xffffffffu, s0, 1);
    s0 += __shfl_xor_sync(0xffffffffu, s0, 2);
    s1 += __shfl_xor_sync(0xffffffffu, s1, 1);
    s1 += __shfl_xor_sync(0xffffffffu, s1, 2);
    const float r0s = 1.f / s0, r1s = 1.f / s1;

    uint32_t* Ps = Ks;
#pragma unroll
    for (int j = 0; j < 16; j++) {
        const int cc = (j * 8 + 2 * q) ^ sw;
        uint2 o0, o1;
        o0.x = pack2(acc[j][0] * r0s); o0.y = pack2(acc[j][1] * r0s);
        o1.x = pack2(acc[j][2] * r1s); o1.y = pack2(acc[j][3] * r1s);
        *(uint2*)(Ps + (rbase + g) * 128 + cc)     = o0;
        *(uint2*)(Ps + (rbase + g + 8) * 128 + cc) = o1;
    }

    uint32_t* Vt = Qs;
#pragma unroll
    for (int ii = 0; ii < 16; ii++) {
        const int f = wid * 16 + ii;
#pragma unroll
        for (int j = 0; j < 4; j++) {
            const int k = lane + 32 * j;
            const uint32_t vv = Vs[k * 128 + (f ^ ((k & 7) << 2))];
            Vt[f * 128 + (k ^ ((f & 7) << 2))] = vv;
        }
    }
    __syncthreads();

    float acc2[16][4];
#pragma unroll
    for (int j = 0; j < 16; j++)
#pragma unroll
        for (int c = 0; c < 4; c++) acc2[j][c] = 0.f;

#pragma unroll
    for (int kk = 0; kk < 8; kk++) {
        const int c0 = (kk * 16 + 2 * q) ^ sw;
        const int c1 = (kk * 16 + 2 * q + 8) ^ sw;
        uint32_t ah[4], al[4];
        {
            const int rr = rbase + g;
            const uint2 w00 = *(const uint2*)(Ps + rr * 128 + c0);
            const uint2 w10 = *(const uint2*)(Ps + (rr + 8) * 128 + c0);
            const uint2 w01 = *(const uint2*)(Ps + rr * 128 + c1);
            const uint2 w11 = *(const uint2*)(Ps + (rr + 8) * 128 + c1);
            unzip(w00.x, w00.y, ah[0], al[0]);
            unzip(w10.x, w10.y, ah[1], al[1]);
            unzip(w01.x, w01.y, ah[2], al[2]);
            unzip(w11.x, w11.y, ah[3], al[3]);
        }
#pragma unroll
        for (int j = 0; j < 16; j++) {
            const int n0 = j * 8 + g;
            const uint2 u0 = *(const uint2*)(Vt + n0 * 128 + c0);
            const uint2 u1 = *(const uint2*)(Vt + n0 * 128 + c1);
            uint32_t bh0[2], bl0[2];
            unzip(u0.x, u0.y, bh0[0], bl0[0]);
            unzip(u1.x, u1.y, bh0[1], bl0[1]);
            mma3(acc2[j], ah, al, bh0[0], bh0[1], bl0[0], bl0[1]);
        }
    }

#pragma unroll
    for (int j = 0; j < 16; j++) {
        const int c = j * 8 + 2 * q;
        const size_t o0 = obase + (size_t)(rbase + g) * Ee + c;
        const size_t o1 = o0 + (size_t)8 * Ee;
        uint16_t h0, l0, h1, l1;
        split2(acc2[j][0], h0, l0); split2(acc2[j][1], h1, l1);
        *(uint32_t*)(Oh + o0) = (uint32_t)h0 | ((uint32_t)h1 << 16);
        *(uint32_t*)(Ol + o0) = (uint32_t)l0 | ((uint32_t)l1 << 16);
        split2(acc2[j][2], h0, l0); split2(acc2[j][3], h1, l1);
        *(uint32_t*)(Oh + o1) = (uint32_t)h0 | ((uint32_t)h1 << 16);
        *(uint32_t*)(Ol + o1) = (uint32_t)l0 | ((uint32_t)l1 << 16);
    }
}

// ---------------------------------------------------------------------------
// launch
// ---------------------------------------------------------------------------
extern "C" void kernel_launch(void* const* d_in, const int* in_sizes, int n_in,
                              void* d_out, int out_size) {
    (void)in_sizes; (void)n_in; (void)out_size;

    const float* x  = (const float*)d_in[0];
    const float* wq = (const float*)d_in[1];
    const float* bq = (const float*)d_in[2];
    const float* wk = (const float*)d_in[3];
    const float* bk = (const float*)d_in[4];
    const float* wv = (const float*)d_in[5];
    const float* bv = (const float*)d_in[6];
    const float* wo = (const float*)d_in[7];
    const float* bo = (const float*)d_in[8];
    const float* w1 = (const float*)d_in[9];
    const float* b1 = (const float*)d_in[10];
    const float* w2 = (const float*)d_in[11];
    const float* b2 = (const float*)d_in[12];
    float* out = (float*)d_out;

    uint16_t *xh, *xl, *ath, *atl, *x1h, *x1l, *hh, *hl;
    uint16_t *wqkvh, *wqkvl, *woh, *wol, *w1h, *w1l, *w2h, *w2l;
    uint32_t* qkvp;
    float *x1f, *bqkv;
    cudaGetSymbolAddress((void**)&xh, g_xh);     cudaGetSymbolAddress((void**)&xl, g_xl);
    cudaGetSymbolAddress((void**)&qkvp, g_qkvp);
    cudaGetSymbolAddress((void**)&ath, g_ath);   cudaGetSymbolAddress((void**)&atl, g_atl);
    cudaGetSymbolAddress((void**)&x1f, g_x1f);
    cudaGetSymbolAddress((void**)&x1h, g_x1h);   cudaGetSymbolAddress((void**)&x1l, g_x1l);
    cudaGetSymbolAddress((void**)&hh, g_hh);     cudaGetSymbolAddress((void**)&hl, g_hl);
    cudaGetSymbolAddress((void**)&wqkvh, g_wqkvh); cudaGetSymbolAddress((void**)&wqkvl, g_wqkvl);
    cudaGetSymbolAddress((void**)&woh, g_woh);   cudaGetSymbolAddress((void**)&wol, g_wol);
    cudaGetSymbolAddress((void**)&w1h, g_w1h);   cudaGetSymbolAddress((void**)&w1l, g_w1l);
    cudaGetSymbolAddress((void**)&w2h, g_w2h);   cudaGetSymbolAddress((void**)&w2l, g_w2l);
    cudaGetSymbolAddress((void**)&bqkv, g_bqkv);

    cudaFuncSetAttribute(gemm_p<0>, cudaFuncAttributeMaxDynamicSharedMemorySize, SMEM_G);
    cudaFuncSetAttribute(gemm_p<1>, cudaFuncAttributeMaxDynamicSharedMemorySize, SMEM_G);
    cudaFuncSetAttribute(gemm_p<2>, cudaFuncAttributeMaxDynamicSharedMemorySize, SMEM_G);
    cudaFuncSetAttribute(gemm_p<3>, cudaFuncAttributeMaxDynamicSharedMemorySize, SMEM_G);
    cudaFuncSetAttribute(attn_kernel, cudaFuncAttributeMaxDynamicSharedMemorySize, SMEM_ATTN);

    // 0: split x (+ bias concat)
    pack_x<<<12294, 256>>>(x, bq, bk, bv);
    // 1: transpose+split all weights
    tpack_all<<<3072, 256>>>(wq, wk, wv, wo, w1, w2);
    // 2: fused QKV projection -> packed qkv  (grid: N=1536/128 x M=49152/256)
    gemm_p<0><<<dim3(12, 192), 256, SMEM_G>>>(xh, xl, wqkvh, wqkvl, bqkv, nullptr,
                                              nullptr, qkvp, nullptr, nullptr, NQKV, Ee);
    // 3: attention -> planes
    attn_kernel<<<Bb * Hh, 256, SMEM_ATTN>>>(qkvp, ath, atl);
    // 4: x1 = x + attn @ wo + bo  (f32 + planes)
    gemm_p<1><<<dim3(4, 192), 256, SMEM_G>>>(ath, atl, woh, wol, bo, x,
                                             x1f, nullptr, x1h, x1l, Ee, Ee);
    // 5: h = relu(x1 @ w1 + b1)   (planes)   <- ncu -s 5 profiles this launch
    gemm_p<2><<<dim3(16, 192), 256, SMEM_G>>>(x1h, x1l, w1h, w1l, b1, nullptr,
                                              nullptr, nullptr, hh, hl, Ff, Ee);
    // 6: out = x1 + h @ w2 + b2   (f32 final)
    gemm_p<3><<<dim3(4, 192), 256, SMEM_G>>>(hh, hl, w2h, w2l, b2, x1f,
                                             out, nullptr, nullptr, nullptr, Ee, Ff);
}

// round 5
// speedup vs baseline: 1.0648x; 1.0569x over previous
#include <cuda_runtime.h>
#include <cstdint>

// ---------------------------------------------------------------------------
// Transformer block, bf16x3 split-precision mma.sync GEMMs.
// R5: conflict-free 128B-row smem (hi|lo co-located), pointer-increment
// cp.async issued mid-tile. Numerics identical to R4.
// B=384, S=128, E=512, H=4, D=128, F=2048.
// ---------------------------------------------------------------------------

constexpr int Bb = 384, Ss = 128, Ee = 512, Hh = 4, Ff = 2048;
constexpr int MM   = Bb * Ss;          // 49152
constexpr int NQKV = 3 * Ee;           // 1536

// -------------------- scratch (static device arrays) -----------------------
__device__ uint16_t g_xh [(size_t)MM * Ee], g_xl [(size_t)MM * Ee];
__device__ uint32_t g_qkvp[(size_t)MM * NQKV];
__device__ uint16_t g_ath[(size_t)MM * Ee], g_atl[(size_t)MM * Ee];
__device__ float    g_x1f[(size_t)MM * Ee];
__device__ uint16_t g_x1h[(size_t)MM * Ee], g_x1l[(size_t)MM * Ee];
__device__ uint16_t g_hh [(size_t)MM * Ff], g_hl [(size_t)MM * Ff];
__device__ uint16_t g_wqkvh[(size_t)NQKV * Ee], g_wqkvl[(size_t)NQKV * Ee];
__device__ uint16_t g_woh[(size_t)Ee * Ee],  g_wol[(size_t)Ee * Ee];
__device__ uint16_t g_w1h[(size_t)Ff * Ee],  g_w1l[(size_t)Ff * Ee];
__device__ uint16_t g_w2h[(size_t)Ee * Ff],  g_w2l[(size_t)Ee * Ff];
__device__ float    g_bqkv[NQKV];

// -------------------- helpers ----------------------------------------------
__device__ __forceinline__ void split2(float v, uint16_t& h, uint16_t& l) {
    float hf;
    asm("cvt.rn.bf16.f32 %0, %1;" : "=h"(h) : "f"(v));
    asm("cvt.f32.bf16 %0, %1;"    : "=f"(hf) : "h"(h));
    asm("cvt.rn.bf16.f32 %0, %1;" : "=h"(l) : "f"(v - hf));
}
__device__ __forceinline__ uint32_t pack2(float x) {      // (hi | lo<<16)
    uint16_t h, l; split2(x, h, l);
    return (uint32_t)h | ((uint32_t)l << 16);
}
__device__ __forceinline__ uint32_t cvta_s(const void* p) {
    uint32_t a;
    asm("{\n\t.reg .u64 t;\n\tcvta.to.shared.u64 t, %1;\n\tcvt.u32.u64 %0, t;\n\t}"
        : "=r"(a) : "l"(p));
    return a;
}

#define CP16(s, g)  asm volatile("cp.async.cg.shared.global [%0], [%1], 16;" ::"r"(s), "l"(g))
#define CPCOMMIT()  asm volatile("cp.async.commit_group;" ::: "memory")

__device__ __forceinline__ void cpwait(int n) {
    if (n >= 2)      asm volatile("cp.async.wait_group 2;" ::: "memory");
    else if (n == 1) asm volatile("cp.async.wait_group 1;" ::: "memory");
    else             asm volatile("cp.async.wait_group 0;" ::: "memory");
}

#define LDSM4(r0, r1, r2, r3, a) \
    asm volatile("ldmatrix.sync.aligned.m8n8.x4.shared.b16 {%0,%1,%2,%3}, [%4];" \
        : "=r"(r0), "=r"(r1), "=r"(r2), "=r"(r3) : "r"(a))

__device__ __forceinline__ void mma16(float* d, const uint32_t* a,
                                      uint32_t b0, uint32_t b1) {
    asm volatile(
        "mma.sync.aligned.m16n8k16.row.col.f32.bf16.bf16.f32 "
        "{%0,%1,%2,%3}, {%4,%5,%6,%7}, {%8,%9}, {%0,%1,%2,%3};\n"
        : "+f"(d[0]), "+f"(d[1]), "+f"(d[2]), "+f"(d[3])
        : "r"(a[0]), "r"(a[1]), "r"(a[2]), "r"(a[3]), "r"(b0), "r"(b1));
}
__device__ __forceinline__ void unzip(uint32_t w0, uint32_t w1,
                                      uint32_t& hi, uint32_t& lo) {
    asm("prmt.b32 %0, %1, %2, 0x5410;" : "=r"(hi) : "r"(w0), "r"(w1));
    asm("prmt.b32 %0, %1, %2, 0x7632;" : "=r"(lo) : "r"(w0), "r"(w1));
}
__device__ __forceinline__ void mma3(float* d, const uint32_t* ah, const uint32_t* al,
                                     uint32_t bh0, uint32_t bh1,
                                     uint32_t bl0, uint32_t bl1) {
    mma16(d, ah, bh0, bh1);
    mma16(d, al, bh0, bh1);
    mma16(d, ah, bl0, bl1);
}

// ---------------------------------------------------------------------------
// prep kernels (unchanged)
// ---------------------------------------------------------------------------
__global__ void pack_x(const float* __restrict__ x,
                       const float* __restrict__ bq, const float* __restrict__ bk,
                       const float* __restrict__ bv) {
    const int b = blockIdx.x;
    if (b >= 12288) {
        const int i = (b - 12288) * 256 + threadIdx.x;
        if (i < NQKV)
            g_bqkv[i] = i < 512 ? bq[i] : (i < 1024 ? bk[i - 512] : bv[i - 1024]);
        return;
    }
    const size_t base = ((size_t)b * 256 + threadIdx.x) * 8;
    const float4 v0 = *(const float4*)(x + base);
    const float4 v1 = *(const float4*)(x + base + 4);
    uint16_t h[8], l[8];
    split2(v0.x, h[0], l[0]); split2(v0.y, h[1], l[1]);
    split2(v0.z, h[2], l[2]); split2(v0.w, h[3], l[3]);
    split2(v1.x, h[4], l[4]); split2(v1.y, h[5], l[5]);
    split2(v1.z, h[6], l[6]); split2(v1.w, h[7], l[7]);
    uint4 oh, ol;
    oh.x = h[0] | (h[1] << 16); oh.y = h[2] | (h[3] << 16);
    oh.z = h[4] | (h[5] << 16); oh.w = h[6] | (h[7] << 16);
    ol.x = l[0] | (l[1] << 16); ol.y = l[2] | (l[3] << 16);
    ol.z = l[4] | (l[5] << 16); ol.w = l[6] | (l[7] << 16);
    *(uint4*)(g_xh + base) = oh;
    *(uint4*)(g_xl + base) = ol;
}

__global__ void tpack_all(const float* __restrict__ wq, const float* __restrict__ wk,
                          const float* __restrict__ wv, const float* __restrict__ wo,
                          const float* __restrict__ w1, const float* __restrict__ w2) {
    __shared__ uint32_t tile[32][33];
    const int id = blockIdx.x;
    const float* W; uint16_t *Dh, *Dl;
    int Nsrc, Kd, tx, ty, rowoff = 0;
    if (id < 768) {
        const int w = id >> 8, loc = id & 255;
        tx = loc & 15; ty = loc >> 4;
        W = w == 0 ? wq : (w == 1 ? wk : wv);
        Dh = g_wqkvh; Dl = g_wqkvl; Nsrc = 512; Kd = 512; rowoff = w * 512;
    } else if (id < 1024) {
        const int loc = id - 768; tx = loc & 15; ty = loc >> 4;
        W = wo; Dh = g_woh; Dl = g_wol; Nsrc = 512; Kd = 512;
    } else if (id < 2048) {
        const int loc = id - 1024; tx = loc & 63; ty = loc >> 6;
        W = w1; Dh = g_w1h; Dl = g_w1l; Nsrc = 2048; Kd = 512;
    } else {
        const int loc = id - 2048; tx = loc & 15; ty = loc >> 4;
        W = w2; Dh = g_w2h; Dl = g_w2l; Nsrc = 512; Kd = 2048;
    }
    const int kb = ty * 32, nb = tx * 32;
    const int lx = threadIdx.x & 31, ly = threadIdx.x >> 5;
    for (int j = ly; j < 32; j += 8) {
        uint16_t h, l;
        split2(W[(size_t)(kb + j) * Nsrc + nb + lx], h, l);
        tile[j][lx] = (uint32_t)h | ((uint32_t)l << 16);
    }
    __syncthreads();
    for (int j = ly; j < 32; j += 8) {
        const uint32_t u = tile[lx][j];
        const size_t o = (size_t)(rowoff + nb + j) * Kd + kb + lx;
        Dh[o] = (uint16_t)u;
        Dl[o] = (uint16_t)(u >> 16);
    }
}

// ---------------------------------------------------------------------------
// GEMM: C = epi(A[M,K] @ B[N,K]^T + bias [, res]), bf16x3 via ldmatrix+HMMA.
// CTA tile 256x128, BK=32, 4-stage cp.async pipeline, 8 warps (warp 64x64).
// smem row = 128B: chunks 0-3 hi(k0..31), 4-7 lo(k0..31); phys = c ^ (row&7).
// EPI: 0 = packed out; 1 = +res, f32+planes; 2 = relu, planes; 3 = +res, f32.
// ---------------------------------------------------------------------------
constexpr int ST   = 4;
constexpr int A_BYTES = 256 * 128;       // 32768
constexpr int B_OFF   = A_BYTES;         // 32768
constexpr int STGB    = A_BYTES + 128 * 128;   // 49152
constexpr int SMEM_G  = ST * STGB;       // 196608

template <int EPI>
__device__ __forceinline__ void epi2(float* __restrict__ Cf, uint32_t* __restrict__ Cp,
                                     uint16_t* __restrict__ Ch, uint16_t* __restrict__ Cl,
                                     const float* __restrict__ bias,
                                     const float* __restrict__ res,
                                     int r, int c, int N, float v0, float v1) {
    v0 += bias[c]; v1 += bias[c + 1];
    if (EPI == 1 || EPI == 3) {
        const float2 rv = *(const float2*)(res + (size_t)r * N + c);
        v0 += rv.x; v1 += rv.y;
    }
    if (EPI == 2) { v0 = fmaxf(v0, 0.f); v1 = fmaxf(v1, 0.f); }
    if (EPI == 1 || EPI == 3)
        *(float2*)(Cf + (size_t)r * N + c) = make_float2(v0, v1);
    if (EPI == 0) {
        uint2 o; o.x = pack2(v0); o.y = pack2(v1);
        *(uint2*)(Cp + (size_t)r * N + c) = o;
    }
    if (EPI == 1 || EPI == 2) {
        uint16_t h0, l0, h1, l1;
        split2(v0, h0, l0); split2(v1, h1, l1);
        *(uint32_t*)(Ch + (size_t)r * N + c) = (uint32_t)h0 | ((uint32_t)h1 << 16);
        *(uint32_t*)(Cl + (size_t)r * N + c) = (uint32_t)l0 | ((uint32_t)l1 << 16);
    }
}

template <int EPI>
__global__ __launch_bounds__(256, 1)
void gemm_p(const uint16_t* __restrict__ Ah_, const uint16_t* __restrict__ Al_,
            const uint16_t* __restrict__ Bh_, const uint16_t* __restrict__ Bl_,
            const float* __restrict__ bias, const float* __restrict__ res,
            float* __restrict__ Cf, uint32_t* __restrict__ Cp,
            uint16_t* __restrict__ Ch, uint16_t* __restrict__ Cl,
            int Nout, int K) {
    extern __shared__ char smraw[];
    const uint32_t sb = cvta_s(smraw);

    const int tid = threadIdx.x, wid = tid >> 5, lane = tid & 31;
    const int wm = wid >> 1, wn = wid & 1;         // 4(M) x 2(N) warp grid
    const int mB = blockIdx.y * 256, nB = blockIdx.x * 128;
    const int l7 = lane & 7, l8 = (lane >> 3) & 1, l16 = lane >> 4;

    // ---- per-thread load geometry (row = tid>>3 + 32i, chunk = tid&7) ----
    const int trow = tid >> 3, tch = tid & 7;
    const int kofs = (tch & 3) * 8;                // element offset within k-block
    const uint32_t dA0 = trow * 128 + (((uint32_t)tch ^ (trow & 7)) << 4);
    const uint32_t dB0 = B_OFF + dA0;              // same row/chunk pattern
    const uint16_t* gA = (tch < 4 ? Ah_ : Al_) + (size_t)(mB + trow) * K + kofs;
    const uint16_t* gB = (tch < 4 ? Bh_ : Bl_) + (size_t)(nB + trow) * K + kofs;
    const size_t aStep = (size_t)32 * K;           // 32 rows per i

    float acc[4][8][4];
#pragma unroll
    for (int a = 0; a < 4; a++)
#pragma unroll
        for (int b = 0; b < 8; b++)
#pragma unroll
            for (int c = 0; c < 4; c++) acc[a][b][c] = 0.f;

    auto issue = [&](int s) {
        const uint32_t stb = sb + (s & (ST - 1)) * STGB;
        const uint16_t* ga = gA + (size_t)s * 32;
        const uint16_t* gb = gB + (size_t)s * 32;
#pragma unroll
        for (int i = 0; i < 8; i++)
            CP16(stb + dA0 + i * 4096, ga + (size_t)i * aStep);
#pragma unroll
        for (int i = 0; i < 4; i++)
            CP16(stb + dB0 + i * 4096, gb + (size_t)i * aStep);
        CPCOMMIT();
    };

    const int nT = K >> 5;
    for (int s = 0; s < ST - 1 && s < nT; s++) issue(s);

    // per-warp LDSM base rows (row&7 == l7 for all of them)
    const uint32_t raBase[4] = {
        (uint32_t)(wm * 64 + 0 * 16 + l8 * 8 + l7),
        (uint32_t)(wm * 64 + 1 * 16 + l8 * 8 + l7),
        (uint32_t)(wm * 64 + 2 * 16 + l8 * 8 + l7),
        (uint32_t)(wm * 64 + 3 * 16 + l8 * 8 + l7)};
    const uint32_t rbBase[4] = {
        (uint32_t)(wn * 64 + 0 * 16 + l8 * 8 + l7),
        (uint32_t)(wn * 64 + 1 * 16 + l8 * 8 + l7),
        (uint32_t)(wn * 64 + 2 * 16 + l8 * 8 + l7),
        (uint32_t)(wn * 64 + 3 * 16 + l8 * 8 + l7)};

    for (int t = 0; t < nT; t++) {
        const int rem = nT - 1 - t;                // groups issued beyond t
        cpwait(rem < 2 ? rem : 2);
        __syncthreads();

        const uint32_t stb = sb + (t & (ST - 1)) * STGB;
#pragma unroll
        for (int h = 0; h < 2; h++) {
            uint32_t ah[4][4], al[4][4];
#pragma unroll
            for (int mi = 0; mi < 4; mi++) {
                const uint32_t r = raBase[mi];
                const uint32_t base = stb + r * 128;
                const uint32_t ch = (uint32_t)(2 * h + l16) ^ (r & 7);
                const uint32_t cl = (uint32_t)(4 + 2 * h + l16) ^ (r & 7);
                LDSM4(ah[mi][0], ah[mi][1], ah[mi][2], ah[mi][3], base + (ch << 4));
                LDSM4(al[mi][0], al[mi][1], al[mi][2], al[mi][3], base + (cl << 4));
            }
#pragma unroll
            for (int j2 = 0; j2 < 4; j2++) {
                const uint32_t r = rbBase[j2];
                const uint32_t base = stb + B_OFF + r * 128;
                const uint32_t ch = (uint32_t)(2 * h + l16) ^ (r & 7);
                const uint32_t cl = (uint32_t)(4 + 2 * h + l16) ^ (r & 7);
                uint32_t bhm[4], blm[4];
                LDSM4(bhm[0], bhm[1], bhm[2], bhm[3], base + (ch << 4));
                LDSM4(blm[0], blm[1], blm[2], blm[3], base + (cl << 4));
#pragma unroll
                for (int mi = 0; mi < 4; mi++) {
#pragma unroll
                    for (int jj = 0; jj < 2; jj++)
                        mma3(acc[mi][2 * j2 + jj], ah[mi], al[mi],
                             bhm[jj], bhm[2 + jj], blm[jj], blm[2 + jj]);
                }
            }
            if (h == 0 && t + ST - 1 < nT) issue(t + ST - 1);   // hide under MMAs
        }
        __syncthreads();
    }

    // epilogue
#pragma unroll
    for (int mi = 0; mi < 4; mi++) {
        const int r0 = mB + wm * 64 + mi * 16 + (lane >> 2);
#pragma unroll
        for (int nj = 0; nj < 8; nj++) {
            const int c = nB + wn * 64 + nj * 8 + 2 * (lane & 3);
            epi2<EPI>(Cf, Cp, Ch, Cl, bias, res, r0,     c, Nout,
                      acc[mi][nj][0], acc[mi][nj][1]);
            epi2<EPI>(Cf, Cp, Ch, Cl, bias, res, r0 + 8, c, Nout,
                      acc[mi][nj][2], acc[mi][nj][3]);
        }
    }
}

// ---------------------------------------------------------------------------
// Attention (mma.sync bf16x3) — reads packed qkv, writes hi/lo planes.
// ---------------------------------------------------------------------------
constexpr int SMEM_ATTN = 3 * 128 * 128 * 4;    // 196608 B

__global__ __launch_bounds__(256, 1)
void attn_kernel(const uint32_t* __restrict__ qkv,
                 uint16_t* __restrict__ Oh, uint16_t* __restrict__ Ol) {
    extern __shared__ uint32_t sm[];
    uint32_t* Qs = sm;               // 128x128, later V^T
    uint32_t* Ks = sm + 16384;       // 128x128, later P
    uint32_t* Vs = sm + 32768;

    const int tid = threadIdx.x;
    const int bh  = blockIdx.x;
    const size_t rowbase = (size_t)(bh >> 2) * Ss * NQKV + (size_t)(bh & 3) * 128;
    const size_t obase   = (size_t)(bh >> 2) * Ss * Ee   + (size_t)(bh & 3) * 128;

    for (int idx = tid; idx < 128 * 32; idx += 256) {
        const int r = idx >> 5, c4 = (idx & 31) << 2;
        const int sc = c4 ^ ((r & 7) << 2);
        const size_t go = rowbase + (size_t)r * NQKV + c4;
        *(uint4*)(Qs + r * 128 + sc) = *(const uint4*)(qkv + go);
        *(uint4*)(Ks + r * 128 + sc) = *(const uint4*)(qkv + go + 512);
        *(uint4*)(Vs + r * 128 + sc) = *(const uint4*)(qkv + go + 1024);
    }
    __syncthreads();

    const int wid = tid >> 5, lane = tid & 31;
    const int g = lane >> 2, q = lane & 3;
    const int rbase = wid * 16;
    const int sw = g << 2;

    float acc[16][4];
#pragma unroll
    for (int j = 0; j < 16; j++)
#pragma unroll
        for (int c = 0; c < 4; c++) acc[j][c] = 0.f;

#pragma unroll
    for (int kk = 0; kk < 8; kk++) {
        const int c0 = (kk * 16 + 2 * q) ^ sw;
        const int c1 = (kk * 16 + 2 * q + 8) ^ sw;
        uint32_t ah[4], al[4];
        {
            const int r0 = rbase + g;
            const uint2 w00 = *(const uint2*)(Qs + r0 * 128 + c0);
            const uint2 w10 = *(const uint2*)(Qs + (r0 + 8) * 128 + c0);
            const uint2 w01 = *(const uint2*)(Qs + r0 * 128 + c1);
            const uint2 w11 = *(const uint2*)(Qs + (r0 + 8) * 128 + c1);
            unzip(w00.x, w00.y, ah[0], al[0]);
            unzip(w10.x, w10.y, ah[1], al[1]);
            unzip(w01.x, w01.y, ah[2], al[2]);
            unzip(w11.x, w11.y, ah[3], al[3]);
        }
#pragma unroll
        for (int j = 0; j < 16; j++) {
            const int n0 = j * 8 + g;
            const uint2 u0 = *(const uint2*)(Ks + n0 * 128 + c0);
            const uint2 u1 = *(const uint2*)(Ks + n0 * 128 + c1);
            uint32_t bh0[2], bl0[2];
            unzip(u0.x, u0.y, bh0[0], bl0[0]);
            unzip(u1.x, u1.y, bh0[1], bl0[1]);
            mma3(acc[j], ah, al, bh0[0], bh0[1], bl0[0], bl0[1]);
        }
    }
    __syncthreads();

    float m0 = -1e30f, m1 = -1e30f;
#pragma unroll
    for (int j = 0; j < 16; j++) {
        m0 = fmaxf(m0, fmaxf(acc[j][0], acc[j][1]));
        m1 = fmaxf(m1, fmaxf(acc[j][2], acc[j][3]));
    }
    m0 = fmaxf(m0, __shfl_xor_sync(0xffffffffu, m0, 1));
    m0 = fmaxf(m0, __shfl_xor_sync(0xffffffffu, m0, 2));
    m1 = fmaxf(m1, __shfl_xor_sync(0xffffffffu, m1, 1));
    m1 = fmaxf(m1, __shfl_xor_sync(0xffffffffu, m1, 2));
    float s0 = 0.f, s1 = 0.f;
#pragma unroll
    for (int j = 0; j < 16; j++) {
        acc[j][0] = expf(acc[j][0] - m0);
        acc[j][1] = expf(acc[j][1] - m0);
        acc[j][2] = expf(acc[j][2] - m1);
        acc[j][3] = expf(acc[j][3] - m1);
        s0 += acc[j][0] + acc[j][1];
        s1 += acc[j][2] + acc[j][3];
    }
    s0 += __shfl_xor_sync(0xffffffffu, s0, 1);
    s0 += __shfl_xor_sync(0xffffffffu, s0, 2);
    s1 += __shfl_xor_sync(0xffffffffu, s1, 1);
    s1 += __shfl_xor_sync(0xffffffffu, s1, 2);
    const float r0s = 1.f / s0, r1s = 1.f / s1;

    uint32_t* Ps = Ks;
#pragma unroll
    for (int j = 0; j < 16; j++) {
        const int cc = (j * 8 + 2 * q) ^ sw;
        uint2 o0, o1;
        o0.x = pack2(acc[j][0] * r0s); o0.y = pack2(acc[j][1] * r0s);
        o1.x = pack2(acc[j][2] * r1s); o1.y = pack2(acc[j][3] * r1s);
        *(uint2*)(Ps + (rbase + g) * 128 + cc)     = o0;
        *(uint2*)(Ps + (rbase + g + 8) * 128 + cc) = o1;
    }

    uint32_t* Vt = Qs;
#pragma unroll
    for (int ii = 0; ii < 16; ii++) {
        const int f = wid * 16 + ii;
#pragma unroll
        for (int j = 0; j < 4; j++) {
            const int k = lane + 32 * j;
            const uint32_t vv = Vs[k * 128 + (f ^ ((k & 7) << 2))];
            Vt[f * 128 + (k ^ ((f & 7) << 2))] = vv;
        }
    }
    __syncthreads();

    float acc2[16][4];
#pragma unroll
    for (int j = 0; j < 16; j++)
#pragma unroll
        for (int c = 0; c < 4; c++) acc2[j][c] = 0.f;

#pragma unroll
    for (int kk = 0; kk < 8; kk++) {
        const int c0 = (kk * 16 + 2 * q) ^ sw;
        const int c1 = (kk * 16 + 2 * q + 8) ^ sw;
        uint32_t ah[4], al[4];
        {
            const int rr = rbase + g;
            const uint2 w00 = *(const uint2*)(Ps + rr * 128 + c0);
            const uint2 w10 = *(const uint2*)(Ps + (rr + 8) * 128 + c0);
            const uint2 w01 = *(const uint2*)(Ps + rr * 128 + c1);
            const uint2 w11 = *(const uint2*)(Ps + (rr + 8) * 128 + c1);
            unzip(w00.x, w00.y, ah[0], al[0]);
            unzip(w10.x, w10.y, ah[1], al[1]);
            unzip(w01.x, w01.y, ah[2], al[2]);
            unzip(w11.x, w11.y, ah[3], al[3]);
        }
#pragma unroll
        for (int j = 0; j < 16; j++) {
            const int n0 = j * 8 + g;
            const uint2 u0 = *(const uint2*)(Vt + n0 * 128 + c0);
            const uint2 u1 = *(const uint2*)(Vt + n0 * 128 + c1);
            uint32_t bh0[2], bl0[2];
            unzip(u0.x, u0.y, bh0[0], bl0[0]);
            unzip(u1.x, u1.y, bh0[1], bl0[1]);
            mma3(acc2[j], ah, al, bh0[0], bh0[1], bl0[0], bl0[1]);
        }
    }

#pragma unroll
    for (int j = 0; j < 16; j++) {
        const int c = j * 8 + 2 * q;
        const size_t o0 = obase + (size_t)(rbase + g) * Ee + c;
        const size_t o1 = o0 + (size_t)8 * Ee;
        uint16_t h0, l0, h1, l1;
        split2(acc2[j][0], h0, l0); split2(acc2[j][1], h1, l1);
        *(uint32_t*)(Oh + o0) = (uint32_t)h0 | ((uint32_t)h1 << 16);
        *(uint32_t*)(Ol + o0) = (uint32_t)l0 | ((uint32_t)l1 << 16);
        split2(acc2[j][2], h0, l0); split2(acc2[j][3], h1, l1);
        *(uint32_t*)(Oh + o1) = (uint32_t)h0 | ((uint32_t)h1 << 16);
        *(uint32_t*)(Ol + o1) = (uint32_t)l0 | ((uint32_t)l1 << 16);
    }
}

// ---------------------------------------------------------------------------
// launch
// ---------------------------------------------------------------------------
extern "C" void kernel_launch(void* const* d_in, const int* in_sizes, int n_in,
                              void* d_out, int out_size) {
    (void)in_sizes; (void)n_in; (void)out_size;

    const float* x  = (const float*)d_in[0];
    const float* wq = (const float*)d_in[1];
    const float* bq = (const float*)d_in[2];
    const float* wk = (const float*)d_in[3];
    const float* bk = (const float*)d_in[4];
    const float* wv = (const float*)d_in[5];
    const float* bv = (const float*)d_in[6];
    const float* wo = (const float*)d_in[7];
    const float* bo = (const float*)d_in[8];
    const float* w1 = (const float*)d_in[9];
    const float* b1 = (const float*)d_in[10];
    const float* w2 = (const float*)d_in[11];
    const float* b2 = (const float*)d_in[12];
    float* out = (float*)d_out;

    uint16_t *xh, *xl, *ath, *atl, *x1h, *x1l, *hh, *hl;
    uint16_t *wqkvh, *wqkvl, *woh, *wol, *w1h, *w1l, *w2h, *w2l;
    uint32_t* qkvp;
    float *x1f, *bqkv;
    cudaGetSymbolAddress((void**)&xh, g_xh);     cudaGetSymbolAddress((void**)&xl, g_xl);
    cudaGetSymbolAddress((void**)&qkvp, g_qkvp);
    cudaGetSymbolAddress((void**)&ath, g_ath);   cudaGetSymbolAddress((void**)&atl, g_atl);
    cudaGetSymbolAddress((void**)&x1f, g_x1f);
    cudaGetSymbolAddress((void**)&x1h, g_x1h);   cudaGetSymbolAddress((void**)&x1l, g_x1l);
    cudaGetSymbolAddress((void**)&hh, g_hh);     cudaGetSymbolAddress((void**)&hl, g_hl);
    cudaGetSymbolAddress((void**)&wqkvh, g_wqkvh); cudaGetSymbolAddress((void**)&wqkvl, g_wqkvl);
    cudaGetSymbolAddress((void**)&woh, g_woh);   cudaGetSymbolAddress((void**)&wol, g_wol);
    cudaGetSymbolAddress((void**)&w1h, g_w1h);   cudaGetSymbolAddress((void**)&w1l, g_w1l);
    cudaGetSymbolAddress((void**)&w2h, g_w2h);   cudaGetSymbolAddress((void**)&w2l, g_w2l);
    cudaGetSymbolAddress((void**)&bqkv, g_bqkv);

    cudaFuncSetAttribute(gemm_p<0>, cudaFuncAttributeMaxDynamicSharedMemorySize, SMEM_G);
    cudaFuncSetAttribute(gemm_p<1>, cudaFuncAttributeMaxDynamicSharedMemorySize, SMEM_G);
    cudaFuncSetAttribute(gemm_p<2>, cudaFuncAttributeMaxDynamicSharedMemorySize, SMEM_G);
    cudaFuncSetAttribute(gemm_p<3>, cudaFuncAttributeMaxDynamicSharedMemorySize, SMEM_G);
    cudaFuncSetAttribute(attn_kernel, cudaFuncAttributeMaxDynamicSharedMemorySize, SMEM_ATTN);

    // 0: split x (+ bias concat)
    pack_x<<<12294, 256>>>(x, bq, bk, bv);
    // 1: transpose+split all weights
    tpack_all<<<3072, 256>>>(wq, wk, wv, wo, w1, w2);
    // 2: fused QKV projection -> packed qkv  (grid: N=1536/128 x M=49152/256)
    gemm_p<0><<<dim3(12, 192), 256, SMEM_G>>>(xh, xl, wqkvh, wqkvl, bqkv, nullptr,
                                              nullptr, qkvp, nullptr, nullptr, NQKV, Ee);
    // 3: attention -> planes
    attn_kernel<<<Bb * Hh, 256, SMEM_ATTN>>>(qkvp, ath, atl);
    // 4: x1 = x + attn @ wo + bo  (f32 + planes)
    gemm_p<1><<<dim3(4, 192), 256, SMEM_G>>>(ath, atl, woh, wol, bo, x,
                                             x1f, nullptr, x1h, x1l, Ee, Ee);
    // 5: h = relu(x1 @ w1 + b1)   (planes)
    gemm_p<2><<<dim3(16, 192), 256, SMEM_G>>>(x1h, x1l, w1h, w1l, b1, nullptr,
                                              nullptr, nullptr, hh, hl, Ff, Ee);
    // 6: out = x1 + h @ w2 + b2   (f32 final)
    gemm_p<3><<<dim3(4, 192), 256, SMEM_G>>>(hh, hl, w2h, w2l, b2, x1f,
                                             out, nullptr, nullptr, nullptr, Ee, Ff);
}

// round 6
// speedup vs baseline: 1.0689x; 1.0039x over previous
#include <cuda_runtime.h>
#include <cstdint>

// ---------------------------------------------------------------------------
// Transformer block, bf16x3 split-precision mma.sync GEMMs.
// R6: single-barrier multistage GEMM pipeline; attention fully on bf16 planes
// with ldmatrix (+ ldmatrix.trans for V^T fragments); merged prep kernel.
// B=384, S=128, E=512, H=4, D=128, F=2048.
// ---------------------------------------------------------------------------

constexpr int Bb = 384, Ss = 128, Ee = 512, Hh = 4, Ff = 2048;
constexpr int MM   = Bb * Ss;          // 49152
constexpr int NQKV = 3 * Ee;           // 1536

// -------------------- scratch (static device arrays) -----------------------
__device__ uint16_t g_xh [(size_t)MM * Ee], g_xl [(size_t)MM * Ee];
__device__ uint16_t g_qh [(size_t)MM * NQKV], g_ql [(size_t)MM * NQKV];
__device__ uint16_t g_ath[(size_t)MM * Ee], g_atl[(size_t)MM * Ee];
__device__ float    g_x1f[(size_t)MM * Ee];
__device__ uint16_t g_x1h[(size_t)MM * Ee], g_x1l[(size_t)MM * Ee];
__device__ uint16_t g_hh [(size_t)MM * Ff], g_hl [(size_t)MM * Ff];
__device__ uint16_t g_wqkvh[(size_t)NQKV * Ee], g_wqkvl[(size_t)NQKV * Ee];
__device__ uint16_t g_woh[(size_t)Ee * Ee],  g_wol[(size_t)Ee * Ee];
__device__ uint16_t g_w1h[(size_t)Ff * Ee],  g_w1l[(size_t)Ff * Ee];
__device__ uint16_t g_w2h[(size_t)Ee * Ff],  g_w2l[(size_t)Ee * Ff];
__device__ float    g_bqkv[NQKV];

// -------------------- helpers ----------------------------------------------
__device__ __forceinline__ void split2(float v, uint16_t& h, uint16_t& l) {
    float hf;
    asm("cvt.rn.bf16.f32 %0, %1;" : "=h"(h) : "f"(v));
    asm("cvt.f32.bf16 %0, %1;"    : "=f"(hf) : "h"(h));
    asm("cvt.rn.bf16.f32 %0, %1;" : "=h"(l) : "f"(v - hf));
}
__device__ __forceinline__ uint32_t cvta_s(const void* p) {
    uint32_t a;
    asm("{\n\t.reg .u64 t;\n\tcvta.to.shared.u64 t, %1;\n\tcvt.u32.u64 %0, t;\n\t}"
        : "=r"(a) : "l"(p));
    return a;
}

#define CP16(s, g)  asm volatile("cp.async.cg.shared.global [%0], [%1], 16;" ::"r"(s), "l"(g))
#define CPCOMMIT()  asm volatile("cp.async.commit_group;" ::: "memory")

__device__ __forceinline__ void cpwait(int n) {
    if (n >= 2)      asm volatile("cp.async.wait_group 2;" ::: "memory");
    else if (n == 1) asm volatile("cp.async.wait_group 1;" ::: "memory");
    else             asm volatile("cp.async.wait_group 0;" ::: "memory");
}

#define LDSM4(r0, r1, r2, r3, a) \
    asm volatile("ldmatrix.sync.aligned.m8n8.x4.shared.b16 {%0,%1,%2,%3}, [%4];" \
        : "=r"(r0), "=r"(r1), "=r"(r2), "=r"(r3) : "r"(a))
#define LDSM4T(r0, r1, r2, r3, a) \
    asm volatile("ldmatrix.sync.aligned.m8n8.x4.trans.shared.b16 {%0,%1,%2,%3}, [%4];" \
        : "=r"(r0), "=r"(r1), "=r"(r2), "=r"(r3) : "r"(a))
#define STS32(a, v) asm volatile("st.shared.b32 [%0], %1;" ::"r"(a), "r"(v) : "memory")

__device__ __forceinline__ void mma16(float* d, const uint32_t* a,
                                      uint32_t b0, uint32_t b1) {
    asm volatile(
        "mma.sync.aligned.m16n8k16.row.col.f32.bf16.bf16.f32 "
        "{%0,%1,%2,%3}, {%4,%5,%6,%7}, {%8,%9}, {%0,%1,%2,%3};\n"
        : "+f"(d[0]), "+f"(d[1]), "+f"(d[2]), "+f"(d[3])
        : "r"(a[0]), "r"(a[1]), "r"(a[2]), "r"(a[3]), "r"(b0), "r"(b1));
}
__device__ __forceinline__ void mma3(float* d, const uint32_t* ah, const uint32_t* al,
                                     uint32_t bh0, uint32_t bh1,
                                     uint32_t bl0, uint32_t bl1) {
    mma16(d, ah, bh0, bh1);
    mma16(d, al, bh0, bh1);
    mma16(d, ah, bl0, bl1);
}

// ---------------------------------------------------------------------------
// merged prep: split x + concat bias + transpose/split all weights
// blocks [0,12288): x split; [12288,12294): bias; [12294,15366): weights
// ---------------------------------------------------------------------------
__global__ void prep_all(const float* __restrict__ x,
                         const float* __restrict__ bq, const float* __restrict__ bk,
                         const float* __restrict__ bv,
                         const float* __restrict__ wq, const float* __restrict__ wk,
                         const float* __restrict__ wv, const float* __restrict__ wo,
                         const float* __restrict__ w1, const float* __restrict__ w2) {
    __shared__ uint32_t tile[32][33];
    const int bidx = blockIdx.x;
    if (bidx < 12288) {
        const size_t base = ((size_t)bidx * 256 + threadIdx.x) * 8;
        const float4 v0 = *(const float4*)(x + base);
        const float4 v1 = *(const float4*)(x + base + 4);
        uint16_t h[8], l[8];
        split2(v0.x, h[0], l[0]); split2(v0.y, h[1], l[1]);
        split2(v0.z, h[2], l[2]); split2(v0.w, h[3], l[3]);
        split2(v1.x, h[4], l[4]); split2(v1.y, h[5], l[5]);
        split2(v1.z, h[6], l[6]); split2(v1.w, h[7], l[7]);
        uint4 oh, ol;
        oh.x = h[0] | (h[1] << 16); oh.y = h[2] | (h[3] << 16);
        oh.z = h[4] | (h[5] << 16); oh.w = h[6] | (h[7] << 16);
        ol.x = l[0] | (l[1] << 16); ol.y = l[2] | (l[3] << 16);
        ol.z = l[4] | (l[5] << 16); ol.w = l[6] | (l[7] << 16);
        *(uint4*)(g_xh + base) = oh;
        *(uint4*)(g_xl + base) = ol;
        return;
    }
    if (bidx < 12294) {
        const int i = (bidx - 12288) * 256 + threadIdx.x;
        if (i < NQKV)
            g_bqkv[i] = i < 512 ? bq[i] : (i < 1024 ? bk[i - 512] : bv[i - 1024]);
        return;
    }
    const int id = bidx - 12294;
    const float* W; uint16_t *Dh, *Dl;
    int Nsrc, Kd, tx, ty, rowoff = 0;
    if (id < 768) {
        const int w = id >> 8, loc = id & 255;
        tx = loc & 15; ty = loc >> 4;
        W = w == 0 ? wq : (w == 1 ? wk : wv);
        Dh = g_wqkvh; Dl = g_wqkvl; Nsrc = 512; Kd = 512; rowoff = w * 512;
    } else if (id < 1024) {
        const int loc = id - 768; tx = loc & 15; ty = loc >> 4;
        W = wo; Dh = g_woh; Dl = g_wol; Nsrc = 512; Kd = 512;
    } else if (id < 2048) {
        const int loc = id - 1024; tx = loc & 63; ty = loc >> 6;
        W = w1; Dh = g_w1h; Dl = g_w1l; Nsrc = 2048; Kd = 512;
    } else {
        const int loc = id - 2048; tx = loc & 15; ty = loc >> 4;
        W = w2; Dh = g_w2h; Dl = g_w2l; Nsrc = 512; Kd = 2048;
    }
    const int kb = ty * 32, nb = tx * 32;
    const int lx = threadIdx.x & 31, ly = threadIdx.x >> 5;
    for (int j = ly; j < 32; j += 8) {
        uint16_t h, l;
        split2(W[(size_t)(kb + j) * Nsrc + nb + lx], h, l);
        tile[j][lx] = (uint32_t)h | ((uint32_t)l << 16);
    }
    __syncthreads();
    for (int j = ly; j < 32; j += 8) {
        const uint32_t u = tile[lx][j];
        const size_t o = (size_t)(rowoff + nb + j) * Kd + kb + lx;
        Dh[o] = (uint16_t)u;
        Dl[o] = (uint16_t)(u >> 16);
    }
}

// ---------------------------------------------------------------------------
// GEMM: C = epi(A[M,K] @ B[N,K]^T + bias [, res]), bf16x3 via ldmatrix+HMMA.
// CTA tile 256x128, BK=32, 4-stage cp.async, single barrier per tile.
// EPI: 0 = planes; 1 = +res, f32+planes; 2 = relu, planes; 3 = +res, f32.
// ---------------------------------------------------------------------------
constexpr int ST   = 4;
constexpr int A_BYTES = 256 * 128;       // 32768
constexpr int B_OFF   = A_BYTES;
constexpr int STGB    = A_BYTES + 128 * 128;   // 49152
constexpr int SMEM_G  = ST * STGB;       // 196608

template <int EPI>
__device__ __forceinline__ void epi2(float* __restrict__ Cf,
                                     uint16_t* __restrict__ Ch, uint16_t* __restrict__ Cl,
                                     const float* __restrict__ bias,
                                     const float* __restrict__ res,
                                     int r, int c, int N, float v0, float v1) {
    v0 += bias[c]; v1 += bias[c + 1];
    if (EPI == 1 || EPI == 3) {
        const float2 rv = *(const float2*)(res + (size_t)r * N + c);
        v0 += rv.x; v1 += rv.y;
    }
    if (EPI == 2) { v0 = fmaxf(v0, 0.f); v1 = fmaxf(v1, 0.f); }
    if (EPI == 1 || EPI == 3)
        *(float2*)(Cf + (size_t)r * N + c) = make_float2(v0, v1);
    if (EPI != 3) {
        uint16_t h0, l0, h1, l1;
        split2(v0, h0, l0); split2(v1, h1, l1);
        *(uint32_t*)(Ch + (size_t)r * N + c) = (uint32_t)h0 | ((uint32_t)h1 << 16);
        *(uint32_t*)(Cl + (size_t)r * N + c) = (uint32_t)l0 | ((uint32_t)l1 << 16);
    }
}

template <int EPI>
__global__ __launch_bounds__(256, 1)
void gemm_p(const uint16_t* __restrict__ Ah_, const uint16_t* __restrict__ Al_,
            const uint16_t* __restrict__ Bh_, const uint16_t* __restrict__ Bl_,
            const float* __restrict__ bias, const float* __restrict__ res,
            float* __restrict__ Cf,
            uint16_t* __restrict__ Ch, uint16_t* __restrict__ Cl,
            int Nout, int K) {
    extern __shared__ char smraw[];
    const uint32_t sb = cvta_s(smraw);

    const int tid = threadIdx.x, wid = tid >> 5, lane = tid & 31;
    const int wm = wid >> 1, wn = wid & 1;         // 4(M) x 2(N) warp grid
    const int mB = blockIdx.y * 256, nB = blockIdx.x * 128;
    const int l7 = lane & 7, l8 = (lane >> 3) & 1, l16 = lane >> 4;

    // per-thread load geometry
    const int trow = tid >> 3, tch = tid & 7;
    const int kofs = (tch & 3) * 8;
    const uint32_t dA0 = trow * 128 + (((uint32_t)tch ^ (trow & 7)) << 4);
    const uint32_t dB0 = B_OFF + dA0;
    const uint16_t* gA = (tch < 4 ? Ah_ : Al_) + (size_t)(mB + trow) * K + kofs;
    const uint16_t* gB = (tch < 4 ? Bh_ : Bl_) + (size_t)(nB + trow) * K + kofs;
    const size_t aStep = (size_t)32 * K;

    float acc[4][8][4];
#pragma unroll
    for (int a = 0; a < 4; a++)
#pragma unroll
        for (int b = 0; b < 8; b++)
#pragma unroll
            for (int c = 0; c < 4; c++) acc[a][b][c] = 0.f;

    auto issue = [&](int s) {
        const uint32_t stb = sb + (s & (ST - 1)) * STGB;
        const uint16_t* ga = gA + (size_t)s * 32;
        const uint16_t* gb = gB + (size_t)s * 32;
#pragma unroll
        for (int i = 0; i < 8; i++)
            CP16(stb + dA0 + i * 4096, ga + (size_t)i * aStep);
#pragma unroll
        for (int i = 0; i < 4; i++)
            CP16(stb + dB0 + i * 4096, gb + (size_t)i * aStep);
        CPCOMMIT();
    };

    const int nT = K >> 5;
    for (int s = 0; s < ST - 1 && s < nT; s++) issue(s);

    const uint32_t raBase[4] = {
        (uint32_t)(wm * 64 + 0 * 16 + l8 * 8 + l7),
        (uint32_t)(wm * 64 + 1 * 16 + l8 * 8 + l7),
        (uint32_t)(wm * 64 + 2 * 16 + l8 * 8 + l7),
        (uint32_t)(wm * 64 + 3 * 16 + l8 * 8 + l7)};
    const uint32_t rbBase[4] = {
        (uint32_t)(wn * 64 + 0 * 16 + l8 * 8 + l7),
        (uint32_t)(wn * 64 + 1 * 16 + l8 * 8 + l7),
        (uint32_t)(wn * 64 + 2 * 16 + l8 * 8 + l7),
        (uint32_t)(wn * 64 + 3 * 16 + l8 * 8 + l7)};

    for (int t = 0; t < nT; t++) {
        const int rem = nT - 1 - t;
        cpwait(rem < 2 ? rem : 2);
        __syncthreads();                       // single barrier per tile
        if (t + ST - 1 < nT) issue(t + ST - 1);   // writes stage (t-1)&3: safe after sync

        const uint32_t stb = sb + (t & (ST - 1)) * STGB;
#pragma unroll
        for (int h = 0; h < 2; h++) {
            uint32_t ah[4][4], al[4][4];
#pragma unroll
            for (int mi = 0; mi < 4; mi++) {
                const uint32_t r = raBase[mi];
                const uint32_t base = stb + r * 128;
                const uint32_t ch = (uint32_t)(2 * h + l16) ^ (r & 7);
                const uint32_t cl = (uint32_t)(4 + 2 * h + l16) ^ (r & 7);
                LDSM4(ah[mi][0], ah[mi][1], ah[mi][2], ah[mi][3], base + (ch << 4));
                LDSM4(al[mi][0], al[mi][1], al[mi][2], al[mi][3], base + (cl << 4));
            }
#pragma unroll
            for (int j2 = 0; j2 < 4; j2++) {
                const uint32_t r = rbBase[j2];
                const uint32_t base = stb + B_OFF + r * 128;
                const uint32_t ch = (uint32_t)(2 * h + l16) ^ (r & 7);
                const uint32_t cl = (uint32_t)(4 + 2 * h + l16) ^ (r & 7);
                uint32_t bhm[4], blm[4];
                LDSM4(bhm[0], bhm[1], bhm[2], bhm[3], base + (ch << 4));
                LDSM4(blm[0], blm[1], blm[2], blm[3], base + (cl << 4));
#pragma unroll
                for (int mi = 0; mi < 4; mi++) {
#pragma unroll
                    for (int jj = 0; jj < 2; jj++)
                        mma3(acc[mi][2 * j2 + jj], ah[mi], al[mi],
                             bhm[jj], bhm[2 + jj], blm[jj], blm[2 + jj]);
                }
            }
        }
    }

    // epilogue
#pragma unroll
    for (int mi = 0; mi < 4; mi++) {
        const int r0 = mB + wm * 64 + mi * 16 + (lane >> 2);
#pragma unroll
        for (int nj = 0; nj < 8; nj++) {
            const int c = nB + wn * 64 + nj * 8 + 2 * (lane & 3);
            epi2<EPI>(Cf, Ch, Cl, bias, res, r0,     c, Nout,
                      acc[mi][nj][0], acc[mi][nj][1]);
            epi2<EPI>(Cf, Ch, Cl, bias, res, r0 + 8, c, Nout,
                      acc[mi][nj][2], acc[mi][nj][3]);
        }
    }
}

// ---------------------------------------------------------------------------
// Attention on bf16 planes. One CTA per (b,h). Q/K/V hi+lo planes in smem
// (rows 256B, 16B chunks, phys chunk = c ^ (row&7)). Fragments via ldmatrix;
// V^T B-fragments via ldmatrix.trans. fp32 softmax. Output planes.
// ---------------------------------------------------------------------------
constexpr int SMEM_ATTN = 6 * 32768;     // 196608

__global__ __launch_bounds__(256, 1)
void attn_kernel(const uint16_t* __restrict__ qh, const uint16_t* __restrict__ ql,
                 uint16_t* __restrict__ Oh, uint16_t* __restrict__ Ol) {
    extern __shared__ char smraw[];
    const uint32_t sb = cvta_s(smraw);
    const uint32_t QH = sb, QL = sb + 32768, KH = sb + 65536, KL = sb + 98304;
    const uint32_t VH = sb + 131072, VL = sb + 163840;

    const int tid = threadIdx.x;
    const int bh  = blockIdx.x;
    const int bb = bh >> 2, head = bh & 3;
    const size_t rowbase = (size_t)bb * Ss * NQKV;
    const int coloff = head * 128;
    const size_t obase = (size_t)bb * Ss * Ee + (size_t)coloff;

    // load 6 planes x 128 rows x 16 chunks of 16B
#pragma unroll
    for (int i = 0; i < 48; i++) {
        const int idx = tid + i * 256;
        const int p = idx >> 11;                 // 0..5: qh,ql,kh,kl,vh,vl
        const int rem = idx & 2047;
        const int row = rem >> 4, c = rem & 15;
        const uint16_t* base = (p & 1) ? ql : qh;
        const size_t src = rowbase + (size_t)row * NQKV + (p >> 1) * 512 + coloff + c * 8;
        const uint32_t dst = sb + p * 32768 + row * 256 + ((uint32_t)(c ^ (row & 7)) << 4);
        CP16(dst, base + src);
    }
    CPCOMMIT();
    cpwait(0);
    __syncthreads();

    const int wid = tid >> 5, lane = tid & 31;
    const int g = lane >> 2, q = lane & 3;
    const int l7 = lane & 7, l8 = (lane >> 3) & 1, l16 = lane >> 4;
    const int rbase = wid * 16;
    const int ra = rbase + l8 * 8 + l7;          // A-fragment source row

    // ---- phase 1: scores = Q @ K^T ----
    float acc[16][4];
#pragma unroll
    for (int j = 0; j < 16; j++)
#pragma unroll
        for (int c = 0; c < 4; c++) acc[j][c] = 0.f;

#pragma unroll
    for (int kk = 0; kk < 8; kk++) {
        const uint32_t ca = ((uint32_t)((2 * kk + l16) ^ (ra & 7)) << 4) + ra * 256;
        uint32_t ah[4], al[4];
        LDSM4(ah[0], ah[1], ah[2], ah[3], QH + ca);
        LDSM4(al[0], al[1], al[2], al[3], QL + ca);
#pragma unroll
        for (int j2 = 0; j2 < 8; j2++) {
            const int rb = j2 * 16 + l8 * 8 + l7;
            const uint32_t cb = ((uint32_t)((2 * kk + l16) ^ (rb & 7)) << 4) + rb * 256;
            uint32_t bh_[4], bl_[4];
            LDSM4(bh_[0], bh_[1], bh_[2], bh_[3], KH + cb);
            LDSM4(bl_[0], bl_[1], bl_[2], bl_[3], KL + cb);
            mma3(acc[j2 * 2],     ah, al, bh_[0], bh_[2], bl_[0], bl_[2]);
            mma3(acc[j2 * 2 + 1], ah, al, bh_[1], bh_[3], bl_[1], bl_[3]);
        }
    }

    // ---- phase 2: softmax (rows rbase+g, rbase+g+8) ----
    float m0 = -1e30f, m1 = -1e30f;
#pragma unroll
    for (int j = 0; j < 16; j++) {
        m0 = fmaxf(m0, fmaxf(acc[j][0], acc[j][1]));
        m1 = fmaxf(m1, fmaxf(acc[j][2], acc[j][3]));
    }
    m0 = fmaxf(m0, __shfl_xor_sync(0xffffffffu, m0, 1));
    m0 = fmaxf(m0, __shfl_xor_sync(0xffffffffu, m0, 2));
    m1 = fmaxf(m1, __shfl_xor_sync(0xffffffffu, m1, 1));
    m1 = fmaxf(m1, __shfl_xor_sync(0xffffffffu, m1, 2));
    float s0 = 0.f, s1 = 0.f;
#pragma unroll
    for (int j = 0; j < 16; j++) {
        acc[j][0] = expf(acc[j][0] - m0);
        acc[j][1] = expf(acc[j][1] - m0);
        acc[j][2] = expf(acc[j][2] - m1);
        acc[j][3] = expf(acc[j][3] - m1);
        s0 += acc[j][0] + acc[j][1];
        s1 += acc[j][2] + acc[j][3];
    }
    s0 += __shfl_xor_sync(0xffffffffu, s0, 1);
    s0 += __shfl_xor_sync(0xffffffffu, s0, 2);
    s1 += __shfl_xor_sync(0xffffffffu, s1, 1);
    s1 += __shfl_xor_sync(0xffffffffu, s1, 2);
    const float r0s = 1.f / s0, r1s = 1.f / s1;

    // ---- store P planes into Q region (warp-private rows) ----
    const int pr0 = rbase + g, pr1 = pr0 + 8;
#pragma unroll
    for (int j = 0; j < 16; j++) {
        const uint32_t off0 = pr0 * 256 + ((uint32_t)(j ^ (pr0 & 7)) << 4) + 4 * q;
        const uint32_t off1 = pr1 * 256 + ((uint32_t)(j ^ (pr1 & 7)) << 4) + 4 * q;
        uint16_t h0, l0, h1, l1;
        split2(acc[j][0] * r0s, h0, l0); split2(acc[j][1] * r0s, h1, l1);
        STS32(QH + off0, (uint32_t)h0 | ((uint32_t)h1 << 16));
        STS32(QL + off0, (uint32_t)l0 | ((uint32_t)l1 << 16));
        split2(acc[j][2] * r1s, h0, l0); split2(acc[j][3] * r1s, h1, l1);
        STS32(QH + off1, (uint32_t)h0 | ((uint32_t)h1 << 16));
        STS32(QL + off1, (uint32_t)l0 | ((uint32_t)l1 << 16));
    }
    __syncwarp();

    // ---- phase 3: out = P @ V  (V^T fragments via ldmatrix.trans) ----
    float acc2[16][4];
#pragma unroll
    for (int j = 0; j < 16; j++)
#pragma unroll
        for (int c = 0; c < 4; c++) acc2[j][c] = 0.f;

#pragma unroll
    for (int kk = 0; kk < 8; kk++) {
        const uint32_t ca = ((uint32_t)((2 * kk + l16) ^ (ra & 7)) << 4) + ra * 256;
        uint32_t ah[4], al[4];
        LDSM4(ah[0], ah[1], ah[2], ah[3], QH + ca);     // P hi
        LDSM4(al[0], al[1], al[2], al[3], QL + ca);     // P lo
        const int krow = kk * 16 + l8 * 8 + l7;         // V source row (key index)
#pragma unroll
        for (int j2 = 0; j2 < 8; j2++) {
            const int cj = j2 * 2 + l16;                // feature chunk (n-block)
            const uint32_t cb = ((uint32_t)(cj ^ (krow & 7)) << 4) + krow * 256;
            uint32_t vh_[4], vl_[4];
            LDSM4T(vh_[0], vh_[1], vh_[2], vh_[3], VH + cb);
            LDSM4T(vl_[0], vl_[1], vl_[2], vl_[3], VL + cb);
            mma3(acc2[j2 * 2],     ah, al, vh_[0], vh_[1], vl_[0], vl_[1]);
            mma3(acc2[j2 * 2 + 1], ah, al, vh_[2], vh_[3], vl_[2], vl_[3]);
        }
    }

    // ---- output planes ----
#pragma unroll
    for (int j = 0; j < 16; j++) {
        const int c = j * 8 + 2 * q;
        const size_t o0 = obase + (size_t)(rbase + g) * Ee + c;
        const size_t o1 = o0 + (size_t)8 * Ee;
        uint16_t h0, l0, h1, l1;
        split2(acc2[j][0], h0, l0); split2(acc2[j][1], h1, l1);
        *(uint32_t*)(Oh + o0) = (uint32_t)h0 | ((uint32_t)h1 << 16);
        *(uint32_t*)(Ol + o0) = (uint32_t)l0 | ((uint32_t)l1 << 16);
        split2(acc2[j][2], h0, l0); split2(acc2[j][3], h1, l1);
        *(uint32_t*)(Oh + o1) = (uint32_t)h0 | ((uint32_t)h1 << 16);
        *(uint32_t*)(Ol + o1) = (uint32_t)l0 | ((uint32_t)l1 << 16);
    }
}

// ---------------------------------------------------------------------------
// launch
// ---------------------------------------------------------------------------
extern "C" void kernel_launch(void* const* d_in, const int* in_sizes, int n_in,
                              void* d_out, int out_size) {
    (void)in_sizes; (void)n_in; (void)out_size;

    const float* x  = (const float*)d_in[0];
    const float* wq = (const float*)d_in[1];
    const float* bq = (const float*)d_in[2];
    const float* wk = (const float*)d_in[3];
    const float* bk = (const float*)d_in[4];
    const float* wv = (const float*)d_in[5];
    const float* bv = (const float*)d_in[6];
    const float* wo = (const float*)d_in[7];
    const float* bo = (const float*)d_in[8];
    const float* w1 = (const float*)d_in[9];
    const float* b1 = (const float*)d_in[10];
    const float* w2 = (const float*)d_in[11];
    const float* b2 = (const float*)d_in[12];
    float* out = (float*)d_out;

    uint16_t *xh, *xl, *qh, *ql, *ath, *atl, *x1h, *x1l, *hh, *hl;
    uint16_t *wqkvh, *wqkvl, *woh, *wol, *w1h, *w1l, *w2h, *w2l;
    float *x1f, *bqkv;
    cudaGetSymbolAddress((void**)&xh, g_xh);     cudaGetSymbolAddress((void**)&xl, g_xl);
    cudaGetSymbolAddress((void**)&qh, g_qh);     cudaGetSymbolAddress((void**)&ql, g_ql);
    cudaGetSymbolAddress((void**)&ath, g_ath);   cudaGetSymbolAddress((void**)&atl, g_atl);
    cudaGetSymbolAddress((void**)&x1f, g_x1f);
    cudaGetSymbolAddress((void**)&x1h, g_x1h);   cudaGetSymbolAddress((void**)&x1l, g_x1l);
    cudaGetSymbolAddress((void**)&hh, g_hh);     cudaGetSymbolAddress((void**)&hl, g_hl);
    cudaGetSymbolAddress((void**)&wqkvh, g_wqkvh); cudaGetSymbolAddress((void**)&wqkvl, g_wqkvl);
    cudaGetSymbolAddress((void**)&woh, g_woh);   cudaGetSymbolAddress((void**)&wol, g_wol);
    cudaGetSymbolAddress((void**)&w1h, g_w1h);   cudaGetSymbolAddress((void**)&w1l, g_w1l);
    cudaGetSymbolAddress((void**)&w2h, g_w2h);   cudaGetSymbolAddress((void**)&w2l, g_w2l);
    cudaGetSymbolAddress((void**)&bqkv, g_bqkv);

    cudaFuncSetAttribute(gemm_p<0>, cudaFuncAttributeMaxDynamicSharedMemorySize, SMEM_G);
    cudaFuncSetAttribute(gemm_p<1>, cudaFuncAttributeMaxDynamicSharedMemorySize, SMEM_G);
    cudaFuncSetAttribute(gemm_p<2>, cudaFuncAttributeMaxDynamicSharedMemorySize, SMEM_G);
    cudaFuncSetAttribute(gemm_p<3>, cudaFuncAttributeMaxDynamicSharedMemorySize, SMEM_G);
    cudaFuncSetAttribute(attn_kernel, cudaFuncAttributeMaxDynamicSharedMemorySize, SMEM_ATTN);

    // 0: merged prep (x split + bias concat + weight transpose/split)
    prep_all<<<15366, 256>>>(x, bq, bk, bv, wq, wk, wv, wo, w1, w2);
    // 1: fused QKV projection -> q/k/v planes
    gemm_p<0><<<dim3(12, 192), 256, SMEM_G>>>(xh, xl, wqkvh, wqkvl, bqkv, nullptr,
                                              nullptr, qh, ql, NQKV, Ee);
    // 2: attention -> planes
    attn_kernel<<<Bb * Hh, 256, SMEM_ATTN>>>(qh, ql, ath, atl);
    // 3: x1 = x + attn @ wo + bo  (f32 + planes)
    gemm_p<1><<<dim3(4, 192), 256, SMEM_G>>>(ath, atl, woh, wol, bo, x,
                                             x1f, x1h, x1l, Ee, Ee);
    // 4: h = relu(x1 @ w1 + b1)   (planes)
    gemm_p<2><<<dim3(16, 192), 256, SMEM_G>>>(x1h, x1l, w1h, w1l, b1, nullptr,
                                              nullptr, hh, hl, Ff, Ee);
    // 5: out = x1 + h @ w2 + b2   (f32 final)
    gemm_p<3><<<dim3(4, 192), 256, SMEM_G>>>(hh, hl, w2h, w2l, b2, x1f,
                                             out, nullptr, nullptr, Ee, Ff);
}